// round 11
// baseline (speedup 1.0000x reference)
#include <cuda_runtime.h>

#define Bsz   32768
#define Edim  128
#define Fdim  128
#define Gdim  256
#define NFdim 256
#define EPSv  1e-5f

typedef unsigned long long ull;

// ---------------- scratch (device globals: allocation-free; .bss zero-init) ----------
__device__ float g_VALS[(size_t)Bsz * 4 * Edim];   // ent() results, slots 0..3   (64 MB)
__device__ float g_X   [(size_t)Bsz * 8 * Fdim];   // conv out hi, 8 slots/batch (6..7=0)
__device__ float g_Xlo [(size_t)Bsz * 8 * Fdim];   // conv out lo residual
__device__ float g_C   [6 * Fdim];                 // folded role+bias+BN constant
__device__ float g_WcT [Edim * Fdim];              // conv_W val-half, transposed, BN-scaled
__device__ float g_WT  [512 * 128];                // gfcn_W transposed, u/v interleaved, hi
__device__ float g_WTlo[512 * 128];                // lo residual

// ---------------- packed fp32x2 helpers (sm_100+) ----------------
__device__ __forceinline__ void ffma2(ull &d, ull a, ull b){
    asm("fma.rn.f32x2 %0, %1, %2, %0;" : "+l"(d) : "l"(a), "l"(b));
}
__device__ __forceinline__ ull dup2(float x){
    ull r; asm("mov.b64 %0, {%1, %1};" : "=l"(r) : "f"(x)); return r;
}
__device__ __forceinline__ float2 upk(ull v){
    float2 f; asm("mov.b64 {%0, %1}, %2;" : "=f"(f.x), "=f"(f.y) : "l"(v)); return f;
}
// cvt.rna.tf32.f32 has a .b32 destination in PTX -> output constraint must be "=r"
__device__ __forceinline__ float tf32r(float x){
    unsigned y; asm("cvt.rna.tf32.f32 %0, %1;" : "=r"(y) : "f"(x));
    return __uint_as_float(y);
}

// legacy tensor-core MMA: m16n8k8 tf32 (sm_80+, runs on Blackwell fallback HMMA)
__device__ __forceinline__ void mma_tf32(float* d, const unsigned* a, const unsigned* b){
    asm volatile(
        "mma.sync.aligned.m16n8k8.row.col.f32.tf32.tf32.f32 "
        "{%0,%1,%2,%3}, {%4,%5,%6,%7}, {%8,%9}, {%0,%1,%2,%3};"
        : "+f"(d[0]), "+f"(d[1]), "+f"(d[2]), "+f"(d[3])
        : "r"(a[0]), "r"(a[1]), "r"(a[2]), "r"(a[3]), "r"(b[0]), "r"(b[1]));
}

// ---------------- prep: fold roles + BN into constants ----------------
__global__ void kprep(const float* __restrict__ role_emb, const float* __restrict__ conv_W,
                      const float* __restrict__ conv_b, const float* __restrict__ gam,
                      const float* __restrict__ bet, const float* __restrict__ mea,
                      const float* __restrict__ var)
{
    int f = threadIdx.x;
    float sc = gam[f] * rsqrtf(var[f] + EPSv);
    int blk = blockIdx.x;
    if (blk < 6) {
        const int roles[6] = {0, 1, 2, 3, 4, 6};
        __shared__ float rs[Edim];
        rs[f] = role_emb[roles[blk] * Edim + f];
        __syncthreads();
        float d = 0.f;
        const float* cw = conv_W + f * 2 * Edim;
        #pragma unroll 8
        for (int e = 0; e < Edim; e++) d += rs[e] * cw[e];
        g_C[blk * Fdim + f] = (d + conv_b[f] - mea[f]) * sc + bet[f];
    } else {
        for (int e = 0; e < Edim; e++)
            g_WcT[e * Fdim + f] = conv_W[f * 2 * Edim + Edim + e] * sc;
    }
}

// prep gfcn_W: g_WT[n][k] hi + g_WTlo lo, n = 2g+h (h=0 -> W1[k][g], h=1 -> W2[k][g])
__global__ void kprepW(const float* __restrict__ gW)
{
    int idx = blockIdx.x * 256 + threadIdx.x;   // 0..65535
    int n = idx >> 7, k = idx & 127;
    int g = n >> 1, h = n & 1;
    float v = gW[(size_t)(h * 128 + k) * Gdim + g];
    float hi = tf32r(v);
    g_WT[idx] = hi;
    g_WTlo[idx] = tf32r(v - hi);
}

// ---------------- stage 1: gathered ent GEMM (FFMA f32x2) ----------------
__global__ __launch_bounds__(256, 2) void kent(
    const int* __restrict__ aid, const int* __restrict__ evid,
    const int* __restrict__ bid, const int* __restrict__ cid,
    const float* __restrict__ nf, const float* __restrict__ ee,
    const float* __restrict__ nW, const float* __restrict__ nbias)
{
    __shared__ int sid[128];
    __shared__ __align__(16) float As[32 * 130];
    __shared__ __align__(16) float Bs[32 * 128];
    int t = threadIdx.x;
    int r0 = blockIdx.x * 128;
    if (t < 128) {
        int R = r0 + t;
        int b = R >> 2, j = R & 3;
        const int* p = (j == 0) ? aid : (j == 1) ? evid : (j == 2) ? bid : cid;
        sid[t] = p[b];
    }
    __syncthreads();
    int mb = t >> 4, nb = t & 15;
    int m0 = mb * 8, n0 = nb * 8;
    ull acc[4][8];
    #pragma unroll
    for (int i = 0; i < 4; i++)
        #pragma unroll
        for (int j = 0; j < 8; j++) acc[i][j] = 0ULL;

    for (int kc = 0; kc < 8; kc++) {
        int k0 = kc * 32;
        #pragma unroll
        for (int it = 0; it < 16; it++) {
            int idx = t + it * 256;
            int m = idx >> 5, k = idx & 31;
            As[k * 130 + m] = nf[(size_t)sid[m] * NFdim + k0 + k];
        }
        {
            const float4* src = (const float4*)(nW + k0 * Fdim);
            float4* dst = (float4*)Bs;
            #pragma unroll
            for (int it = 0; it < 4; it++) dst[t + it * 256] = src[t + it * 256];
        }
        __syncthreads();
        #pragma unroll 4
        for (int kk = 0; kk < 32; kk++) {
            const ull* ap = (const ull*)(As + kk * 130 + m0);
            ull a0 = ap[0], a1 = ap[1], a2 = ap[2], a3 = ap[3];
            const float4* bp = (const float4*)(Bs + kk * 128 + n0);
            float4 blo = bp[0], bhi = bp[1];
            float bf[8] = {blo.x, blo.y, blo.z, blo.w, bhi.x, bhi.y, bhi.z, bhi.w};
            #pragma unroll
            for (int j = 0; j < 8; j++) {
                ull b2 = dup2(bf[j]);
                ffma2(acc[0][j], a0, b2);
                ffma2(acc[1][j], a1, b2);
                ffma2(acc[2][j], a2, b2);
                ffma2(acc[3][j], a3, b2);
            }
        }
        __syncthreads();
    }

    float4 nb0 = *(const float4*)(nbias + n0);
    float4 nb1 = *(const float4*)(nbias + n0 + 4);
    #pragma unroll
    for (int p = 0; p < 4; p++) {
        float lo[8], hi[8];
        #pragma unroll
        for (int j = 0; j < 8; j++) { float2 v = upk(acc[p][j]); lo[j] = v.x; hi[j] = v.y; }
        #pragma unroll
        for (int h = 0; h < 2; h++) {
            float vv[8];
            #pragma unroll
            for (int j = 0; j < 8; j++) vv[j] = h ? hi[j] : lo[j];
            int m = m0 + 2 * p + h;
            int R = r0 + m;
            const float4* e4 = (const float4*)(ee + (size_t)sid[m] * Edim + n0);
            float4 e0 = e4[0], e1 = e4[1];
            float4 o0, o1;
            o0.x = fmaxf(vv[0] + nb0.x, 0.f) + e0.x;
            o0.y = fmaxf(vv[1] + nb0.y, 0.f) + e0.y;
            o0.z = fmaxf(vv[2] + nb0.z, 0.f) + e0.z;
            o0.w = fmaxf(vv[3] + nb0.w, 0.f) + e0.w;
            o1.x = fmaxf(vv[4] + nb1.x, 0.f) + e1.x;
            o1.y = fmaxf(vv[5] + nb1.y, 0.f) + e1.y;
            o1.z = fmaxf(vv[6] + nb1.z, 0.f) + e1.z;
            o1.w = fmaxf(vv[7] + nb1.w, 0.f) + e1.w;
            float4* dst = (float4*)(g_VALS + (size_t)R * Edim + n0);
            dst[0] = o0; dst[1] = o1;
        }
    }
}

// ---------------- stage 2: conv + BN + relu (FFMA f32x2), writes hi/lo split g_X ------
__global__ __launch_bounds__(256, 2) void kconv(const float* __restrict__ cond,
                                                const float* __restrict__ text)
{
    __shared__ const float* srcp[128];
    __shared__ int sslot[128];
    __shared__ __align__(16) float As[32 * 130];
    __shared__ __align__(16) float Bs[32 * 128];
    int t = threadIdx.x;
    int r0 = blockIdx.x * 128;
    if (t < 128) {
        int r = r0 + t;
        int b = r / 6, s = r - b * 6;
        const float* p;
        if (s < 4)       p = g_VALS + ((size_t)b * 4 + s) * Edim;
        else if (s == 4) p = cond + (size_t)b * Edim;
        else             p = text + (size_t)b * Edim;
        srcp[t] = p; sslot[t] = s;
    }
    __syncthreads();
    int mb = t >> 4, nb = t & 15;
    int m0 = mb * 8, n0 = nb * 8;
    ull acc[4][8];
    #pragma unroll
    for (int i = 0; i < 4; i++)
        #pragma unroll
        for (int j = 0; j < 8; j++) acc[i][j] = 0ULL;

    for (int kc = 0; kc < 4; kc++) {
        int k0 = kc * 32;
        #pragma unroll
        for (int it = 0; it < 16; it++) {
            int idx = t + it * 256;
            int m = idx >> 5, k = idx & 31;
            As[k * 130 + m] = srcp[m][k0 + k];
        }
        {
            const float4* src = (const float4*)(g_WcT + k0 * Fdim);
            float4* dst = (float4*)Bs;
            #pragma unroll
            for (int it = 0; it < 4; it++) dst[t + it * 256] = src[t + it * 256];
        }
        __syncthreads();
        #pragma unroll 4
        for (int kk = 0; kk < 32; kk++) {
            const ull* ap = (const ull*)(As + kk * 130 + m0);
            ull a0 = ap[0], a1 = ap[1], a2 = ap[2], a3 = ap[3];
            const float4* bp = (const float4*)(Bs + kk * 128 + n0);
            float4 blo = bp[0], bhi = bp[1];
            float bf[8] = {blo.x, blo.y, blo.z, blo.w, bhi.x, bhi.y, bhi.z, bhi.w};
            #pragma unroll
            for (int j = 0; j < 8; j++) {
                ull b2 = dup2(bf[j]);
                ffma2(acc[0][j], a0, b2);
                ffma2(acc[1][j], a1, b2);
                ffma2(acc[2][j], a2, b2);
                ffma2(acc[3][j], a3, b2);
            }
        }
        __syncthreads();
    }

    #pragma unroll
    for (int p = 0; p < 4; p++) {
        float lo[8], hi[8];
        #pragma unroll
        for (int j = 0; j < 8; j++) { float2 v = upk(acc[p][j]); lo[j] = v.x; hi[j] = v.y; }
        #pragma unroll
        for (int h = 0; h < 2; h++) {
            float vv[8];
            #pragma unroll
            for (int j = 0; j < 8; j++) vv[j] = h ? hi[j] : lo[j];
            int m = m0 + 2 * p + h;
            int rr = r0 + m;
            int b6 = rr / 6, s6 = rr - b6 * 6;
            const float4* c4 = (const float4*)(g_C + sslot[m] * Fdim + n0);
            float4 c0 = c4[0], c1 = c4[1];
            float cadd[8] = {c0.x, c0.y, c0.z, c0.w, c1.x, c1.y, c1.z, c1.w};
            float fh[8], fl[8];
            #pragma unroll
            for (int j = 0; j < 8; j++) {
                float f = fmaxf(vv[j] + cadd[j], 0.f);
                fh[j] = tf32r(f);
                fl[j] = tf32r(f - fh[j]);
            }
            size_t off = ((size_t)b6 * 8 + s6) * Fdim + n0;
            float4* dh = (float4*)(g_X + off);
            dh[0] = make_float4(fh[0], fh[1], fh[2], fh[3]);
            dh[1] = make_float4(fh[4], fh[5], fh[6], fh[7]);
            float4* dl = (float4*)(g_Xlo + off);
            dl[0] = make_float4(fl[0], fl[1], fl[2], fl[3]);
            dl[1] = make_float4(fl[4], fl[5], fl[6], fl[7]);
        }
    }
}

// ---------------- stage 3: split-fp32 3-pass tf32 MMA + min-over-6 + relu out --------
// D = A_hi B_hi + A_lo B_hi + A_hi B_lo  (lo.lo dropped, ~2^-22 relative)
// CTA: M128 x N128 x K128, K in 2 chunks of 64. grid (4, 2048), x = N-tile.
// Smem per chunk: A_hi/A_lo 64 fb x 32 x uint4 (32KB each), B_hi/B_lo 128 fb x 32 x
// uint2 (32KB each) = 128KB. fb = mtile*8+ks (A) / ntile*8+ks (B), ks local 0..7.
// Epilogue identical to verified single-pass version.
#define KUV_SMEM (131072)
__global__ __launch_bounds__(256, 1) void kuv_mma(const float* __restrict__ gb,
                                                  float* __restrict__ out)
{
    extern __shared__ char dsm[];
    float4* Ah4 = (float4*)dsm;                   // 64 fb * 32 * 16B = 32KB
    float4* Al4 = (float4*)(dsm + 32768);
    float2* Bh2 = (float2*)(dsm + 65536);         // 128 fb * 32 * 8B = 32KB
    float2* Bl2 = (float2*)(dsm + 98304);
    int t = threadIdx.x, w = t >> 5, l = t & 31;
    int ntB = blockIdx.x, mtB = blockIdx.y;

    int wmFb = (w >> 2) * 32;   // warpM * 4 mtiles * 8 ksteps
    int wnFb = (w & 3) * 32;    // warpN * 4 ntiles * 8 ksteps
    float d[4][4][4];
    #pragma unroll
    for (int mi = 0; mi < 4; mi++)
        #pragma unroll
        for (int ni = 0; ni < 4; ni++)
            #pragma unroll
            for (int r = 0; r < 4; r++) d[mi][ni][r] = 0.f;

    for (int kc = 0; kc < 2; kc++) {
        if (kc) __syncthreads();   // protect previous chunk's fragments until consumed
        // ---- fill A hi/lo fragments ----
        {
            const float* sh = g_X   + (size_t)mtB * 128 * 128;
            const float* sl = g_Xlo + (size_t)mtB * 128 * 128;
            #pragma unroll
            for (int it = 0; it < 8; it++) {
                int u = t + it * 256;             // 0..2047
                int fb = u >> 5, tl = u & 31;
                int mtile = fb >> 3, ks = fb & 7;
                int r = mtile * 16 + (tl >> 2);
                int c = (kc * 8 + ks) * 8 + (tl & 3);
                Ah4[u] = make_float4(sh[r * 128 + c], sh[(r + 8) * 128 + c],
                                     sh[r * 128 + c + 4], sh[(r + 8) * 128 + c + 4]);
                Al4[u] = make_float4(sl[r * 128 + c], sl[(r + 8) * 128 + c],
                                     sl[r * 128 + c + 4], sl[(r + 8) * 128 + c + 4]);
            }
        }
        // ---- fill B hi/lo fragments ----
        {
            const float* sh = g_WT   + (size_t)ntB * 128 * 128;
            const float* sl = g_WTlo + (size_t)ntB * 128 * 128;
            #pragma unroll
            for (int it = 0; it < 16; it++) {
                int u = t + it * 256;             // 0..4095
                int fb = u >> 5, tl = u & 31;
                int ntile = fb >> 3, ks = fb & 7;
                int n = ntile * 8 + (tl >> 2);
                int k = (kc * 8 + ks) * 8 + (tl & 3);
                Bh2[u] = make_float2(sh[n * 128 + k], sh[n * 128 + k + 4]);
                Bl2[u] = make_float2(sl[n * 128 + k], sl[n * 128 + k + 4]);
            }
        }
        __syncthreads();

        #pragma unroll 2
        for (int ks = 0; ks < 8; ks++) {
            uint4 ah[4], al[4]; uint2 bh[4], bl[4];
            #pragma unroll
            for (int mi = 0; mi < 4; mi++) {
                ah[mi] = ((const uint4*)Ah4)[(wmFb + mi * 8 + ks) * 32 + l];
                al[mi] = ((const uint4*)Al4)[(wmFb + mi * 8 + ks) * 32 + l];
            }
            #pragma unroll
            for (int ni = 0; ni < 4; ni++) {
                bh[ni] = ((const uint2*)Bh2)[(wnFb + ni * 8 + ks) * 32 + l];
                bl[ni] = ((const uint2*)Bl2)[(wnFb + ni * 8 + ks) * 32 + l];
            }
            #pragma unroll
            for (int mi = 0; mi < 4; mi++)
                #pragma unroll
                for (int ni = 0; ni < 4; ni++) {
                    mma_tf32(d[mi][ni], (const unsigned*)&al[mi], (const unsigned*)&bh[ni]);
                    mma_tf32(d[mi][ni], (const unsigned*)&ah[mi], (const unsigned*)&bl[ni]);
                    mma_tf32(d[mi][ni], (const unsigned*)&ah[mi], (const unsigned*)&bh[ni]);
                }
        }
    }

    // ---- epilogue: mask pad slots, butterfly min over slots, u+v+bias, relu ----
    int slot = l >> 2, c = l & 3;
    if (slot >= 6) {
        #pragma unroll
        for (int mi = 0; mi < 4; mi++)
            #pragma unroll
            for (int ni = 0; ni < 4; ni++)
                #pragma unroll
                for (int r = 0; r < 4; r++) d[mi][ni][r] = 1e30f;
    }
    #pragma unroll
    for (int mi = 0; mi < 4; mi++)
        #pragma unroll
        for (int ni = 0; ni < 4; ni++)
            #pragma unroll
            for (int r = 0; r < 4; r++) {
                float v = d[mi][ni][r];
                v = fminf(v, __shfl_xor_sync(0xFFFFFFFFu, v, 4));
                v = fminf(v, __shfl_xor_sync(0xFFFFFFFFu, v, 8));
                v = fminf(v, __shfl_xor_sync(0xFFFFFFFFu, v, 16));
                d[mi][ni][r] = v;
            }

    int gBase = ntB * 64 + (w & 3) * 16;
    float gbv[4];
    #pragma unroll
    for (int ni = 0; ni < 4; ni++) gbv[ni] = gb[gBase + ni * 4 + c];

    int bbBase = mtB * 16 + (w >> 2) * 8;
    #pragma unroll
    for (int mi = 0; mi < 4; mi++) {
        #pragma unroll
        for (int half = 0; half < 2; half++) {
            int bb = bbBase + mi * 2 + half;
            bool mine = (slot == half * 4 + mi);
            #pragma unroll
            for (int ni = 0; ni < 4; ni++) {
                float uu = d[mi][ni][half * 2 + 0];
                float vv = d[mi][ni][half * 2 + 1];
                float o = fmaxf(uu + vv + gbv[ni], 0.f);
                if (mine) out[(size_t)bb * Gdim + gBase + ni * 4 + c] = o;
            }
        }
    }
}

// ---------------- launcher ----------------
extern "C" void kernel_launch(void* const* d_in, const int* in_sizes, int n_in,
                              void* d_out, int out_size)
{
    const int*   a_ids = (const int*)d_in[0];
    const int*   b_ids = (const int*)d_in[1];
    const int*   c_ids = (const int*)d_in[2];
    const int*   e_ids = (const int*)d_in[3];
    const float* nf    = (const float*)d_in[4];
    const float* cond  = (const float*)d_in[5];
    const float* text  = (const float*)d_in[6];
    const float* ee    = (const float*)d_in[7];
    const float* re    = (const float*)d_in[8];
    const float* nW    = (const float*)d_in[9];
    const float* nbias = (const float*)d_in[10];
    const float* cW    = (const float*)d_in[11];
    const float* cb    = (const float*)d_in[12];
    const float* gam   = (const float*)d_in[13];
    const float* bet   = (const float*)d_in[14];
    const float* mea   = (const float*)d_in[15];
    const float* var   = (const float*)d_in[16];
    const float* gW    = (const float*)d_in[17];
    const float* gbias = (const float*)d_in[18];
    float* out = (float*)d_out;

    cudaFuncSetAttribute(kuv_mma, cudaFuncAttributeMaxDynamicSharedMemorySize, KUV_SMEM);

    kprep<<<7, 128>>>(re, cW, cb, gam, bet, mea, var);
    kprepW<<<256, 256>>>(gW);
    kent<<<(4 * Bsz) / 128, 256>>>(a_ids, e_ids, b_ids, c_ids, nf, ee, nW, nbias);
    kconv<<<(6 * Bsz) / 128, 256>>>(cond, text);
    kuv_mma<<<dim3(4, 2048), 256, KUV_SMEM>>>(gbias, out);
}

// round 13
// speedup vs baseline: 1.6092x; 1.6092x over previous
#include <cuda_runtime.h>
#include <cuda_bf16.h>

#define Bsz   32768
#define Edim  128
#define Fdim  128
#define Gdim  256
#define NFdim 256
#define EPSv  1e-5f

typedef unsigned long long ull;

// ---------------- scratch (device globals: allocation-free; .bss zero-init) ----------
__device__ float g_VALS[(size_t)Bsz * 4 * Edim];     // ent() results, slots 0..3 (64 MB)
// A fragments for stage 3: [split 2][mtB 2048][fb 64][lane 32] uint4  (134 MB)
//   fb = mtile*8 + kst; pad rows (slots 6,7) never written -> stay 0
__device__ uint4 g_XF[(size_t)2 * 2048 * 64 * 32];
// B fragments: [split 2][ntB 4][fb 128][lane 32] uint2  (256 KB)
__device__ uint2 g_WF[(size_t)2 * 4 * 128 * 32];
__device__ float g_C  [6 * Fdim];                    // folded role+bias+BN constant
__device__ float g_WcT[Edim * Fdim];                 // conv_W val-half, transposed, scaled

// ---------------- packed fp32x2 helpers (sm_100+) ----------------
__device__ __forceinline__ void ffma2(ull &d, ull a, ull b){
    asm("fma.rn.f32x2 %0, %1, %2, %0;" : "+l"(d) : "l"(a), "l"(b));
}
__device__ __forceinline__ ull dup2(float x){
    ull r; asm("mov.b64 %0, {%1, %1};" : "=l"(r) : "f"(x)); return r;
}
__device__ __forceinline__ float2 upk(ull v){
    float2 f; asm("mov.b64 {%0, %1}, %2;" : "=f"(f.x), "=f"(f.y) : "l"(v)); return f;
}

// ---------------- bf16 split helpers ----------------
__device__ __forceinline__ float bf16f(float a){
    return __bfloat162float(__float2bfloat16_rn(a));
}
__device__ __forceinline__ unsigned pack2(float a, float b){
    unsigned ua = (unsigned)__bfloat16_as_ushort(__float2bfloat16_rn(a));
    unsigned ub = (unsigned)__bfloat16_as_ushort(__float2bfloat16_rn(b));
    return ua | (ub << 16);
}

// bf16 tensor-core MMA: m16n8k16 (sm_80+)
__device__ __forceinline__ void mma_bf16(float* d, const unsigned* a, const unsigned* b){
    asm volatile(
        "mma.sync.aligned.m16n8k16.row.col.f32.bf16.bf16.f32 "
        "{%0,%1,%2,%3}, {%4,%5,%6,%7}, {%8,%9}, {%0,%1,%2,%3};"
        : "+f"(d[0]), "+f"(d[1]), "+f"(d[2]), "+f"(d[3])
        : "r"(a[0]), "r"(a[1]), "r"(a[2]), "r"(a[3]), "r"(b[0]), "r"(b[1]));
}

// ---------------- prep: fold roles + BN into constants ----------------
__global__ void kprep(const float* __restrict__ role_emb, const float* __restrict__ conv_W,
                      const float* __restrict__ conv_b, const float* __restrict__ gam,
                      const float* __restrict__ bet, const float* __restrict__ mea,
                      const float* __restrict__ var)
{
    int f = threadIdx.x;
    float sc = gam[f] * rsqrtf(var[f] + EPSv);
    int blk = blockIdx.x;
    if (blk < 6) {
        const int roles[6] = {0, 1, 2, 3, 4, 6};
        __shared__ float rs[Edim];
        rs[f] = role_emb[roles[blk] * Edim + f];
        __syncthreads();
        float d = 0.f;
        const float* cw = conv_W + f * 2 * Edim;
        #pragma unroll 8
        for (int e = 0; e < Edim; e++) d += rs[e] * cw[e];
        g_C[blk * Fdim + f] = (d + conv_b[f] - mea[f]) * sc + bet[f];
    } else {
        for (int e = 0; e < Edim; e++)
            g_WcT[e * Fdim + f] = conv_W[f * 2 * Edim + Edim + e] * sc;
    }
}

// prep gfcn_W into B fragments, bf16 2-split. n = 2g+h (h=0 -> W1[k][g], h=1 -> W2).
// One thread per (n, k-pair p): k = 2p, 2p+1.
__global__ void kprepW(const float* __restrict__ gW)
{
    int idx = blockIdx.x * 256 + threadIdx.x;   // 0..32767
    int n = idx >> 6, p = idx & 63;
    int g = n >> 1, h = n & 1;
    float v0 = gW[(size_t)(h * 128 + 2 * p) * Gdim + g];
    float v1 = gW[(size_t)(h * 128 + 2 * p + 1) * Gdim + g];
    unsigned hp = pack2(v0, v1);
    unsigned lp = pack2(v0 - bf16f(v0), v1 - bf16f(v1));
    int kst = p >> 3, pi = p & 7, kp = pi & 3, reg = pi >> 2;
    int ntB = n >> 7, ntile = (n & 127) >> 3, lane = (n & 7) * 4 + kp;
    int fb = ntile * 8 + kst;
    unsigned* dst = (unsigned*)g_WF;
    size_t i0 = (((size_t)ntB * 128 + fb) * 32 + lane) * 2 + reg;
    size_t plane = (size_t)4 * 128 * 32 * 2;
    dst[i0] = hp;
    dst[plane + i0] = lp;
}

// ---------------- stage 1: gathered ent GEMM (FFMA f32x2) ----------------
__global__ __launch_bounds__(256, 2) void kent(
    const int* __restrict__ aid, const int* __restrict__ evid,
    const int* __restrict__ bid, const int* __restrict__ cid,
    const float* __restrict__ nf, const float* __restrict__ ee,
    const float* __restrict__ nW, const float* __restrict__ nbias)
{
    __shared__ int sid[128];
    __shared__ __align__(16) float As[32 * 130];
    __shared__ __align__(16) float Bs[32 * 128];
    int t = threadIdx.x;
    int r0 = blockIdx.x * 128;
    if (t < 128) {
        int R = r0 + t;
        int b = R >> 2, j = R & 3;
        const int* p = (j == 0) ? aid : (j == 1) ? evid : (j == 2) ? bid : cid;
        sid[t] = p[b];
    }
    __syncthreads();
    int mb = t >> 4, nb = t & 15;
    int m0 = mb * 8, n0 = nb * 8;
    ull acc[4][8];
    #pragma unroll
    for (int i = 0; i < 4; i++)
        #pragma unroll
        for (int j = 0; j < 8; j++) acc[i][j] = 0ULL;

    for (int kc = 0; kc < 8; kc++) {
        int k0 = kc * 32;
        #pragma unroll
        for (int it = 0; it < 16; it++) {
            int idx = t + it * 256;
            int m = idx >> 5, k = idx & 31;
            As[k * 130 + m] = nf[(size_t)sid[m] * NFdim + k0 + k];
        }
        {
            const float4* src = (const float4*)(nW + k0 * Fdim);
            float4* dst = (float4*)Bs;
            #pragma unroll
            for (int it = 0; it < 4; it++) dst[t + it * 256] = src[t + it * 256];
        }
        __syncthreads();
        #pragma unroll 4
        for (int kk = 0; kk < 32; kk++) {
            const ull* ap = (const ull*)(As + kk * 130 + m0);
            ull a0 = ap[0], a1 = ap[1], a2 = ap[2], a3 = ap[3];
            const float4* bp = (const float4*)(Bs + kk * 128 + n0);
            float4 blo = bp[0], bhi = bp[1];
            float bf[8] = {blo.x, blo.y, blo.z, blo.w, bhi.x, bhi.y, bhi.z, bhi.w};
            #pragma unroll
            for (int j = 0; j < 8; j++) {
                ull b2 = dup2(bf[j]);
                ffma2(acc[0][j], a0, b2);
                ffma2(acc[1][j], a1, b2);
                ffma2(acc[2][j], a2, b2);
                ffma2(acc[3][j], a3, b2);
            }
        }
        __syncthreads();
    }

    float4 nb0 = *(const float4*)(nbias + n0);
    float4 nb1 = *(const float4*)(nbias + n0 + 4);
    #pragma unroll
    for (int p = 0; p < 4; p++) {
        float lo[8], hi[8];
        #pragma unroll
        for (int j = 0; j < 8; j++) { float2 v = upk(acc[p][j]); lo[j] = v.x; hi[j] = v.y; }
        #pragma unroll
        for (int h = 0; h < 2; h++) {
            float vv[8];
            #pragma unroll
            for (int j = 0; j < 8; j++) vv[j] = h ? hi[j] : lo[j];
            int m = m0 + 2 * p + h;
            int R = r0 + m;
            const float4* e4 = (const float4*)(ee + (size_t)sid[m] * Edim + n0);
            float4 e0 = e4[0], e1 = e4[1];
            float4 o0, o1;
            o0.x = fmaxf(vv[0] + nb0.x, 0.f) + e0.x;
            o0.y = fmaxf(vv[1] + nb0.y, 0.f) + e0.y;
            o0.z = fmaxf(vv[2] + nb0.z, 0.f) + e0.z;
            o0.w = fmaxf(vv[3] + nb0.w, 0.f) + e0.w;
            o1.x = fmaxf(vv[4] + nb1.x, 0.f) + e1.x;
            o1.y = fmaxf(vv[5] + nb1.y, 0.f) + e1.y;
            o1.z = fmaxf(vv[6] + nb1.z, 0.f) + e1.z;
            o1.w = fmaxf(vv[7] + nb1.w, 0.f) + e1.w;
            float4* dst = (float4*)(g_VALS + (size_t)R * Edim + n0);
            dst[0] = o0; dst[1] = o1;
        }
    }
}

// ---------------- stage 2: conv + BN + relu, writes bf16-split A FRAGMENTS ----------
// Thread holds row rr (padded R8 = b6*8+s6), cols n0..n0+7 (the stage-3 K dim).
// Its 4 bf16x2 pairs map to one fragment block fb = mtile*8 + (nb>>1),
// lanes row_off*4 + j, component creg = (rin>>3) + 2*(nb&1).
__global__ __launch_bounds__(256, 2) void kconv(const float* __restrict__ cond,
                                                const float* __restrict__ text)
{
    __shared__ const float* srcp[128];
    __shared__ int sslot[128];
    __shared__ __align__(16) float As[32 * 130];
    __shared__ __align__(16) float Bs[32 * 128];
    int t = threadIdx.x;
    int r0 = blockIdx.x * 128;
    if (t < 128) {
        int r = r0 + t;
        int b = r / 6, s = r - b * 6;
        const float* p;
        if (s < 4)       p = g_VALS + ((size_t)b * 4 + s) * Edim;
        else if (s == 4) p = cond + (size_t)b * Edim;
        else             p = text + (size_t)b * Edim;
        srcp[t] = p; sslot[t] = s;
    }
    __syncthreads();
    int mb = t >> 4, nb = t & 15;
    int m0 = mb * 8, n0 = nb * 8;
    ull acc[4][8];
    #pragma unroll
    for (int i = 0; i < 4; i++)
        #pragma unroll
        for (int j = 0; j < 8; j++) acc[i][j] = 0ULL;

    for (int kc = 0; kc < 4; kc++) {
        int k0 = kc * 32;
        #pragma unroll
        for (int it = 0; it < 16; it++) {
            int idx = t + it * 256;
            int m = idx >> 5, k = idx & 31;
            As[k * 130 + m] = srcp[m][k0 + k];
        }
        {
            const float4* src = (const float4*)(g_WcT + k0 * Fdim);
            float4* dst = (float4*)Bs;
            #pragma unroll
            for (int it = 0; it < 4; it++) dst[t + it * 256] = src[t + it * 256];
        }
        __syncthreads();
        #pragma unroll 4
        for (int kk = 0; kk < 32; kk++) {
            const ull* ap = (const ull*)(As + kk * 130 + m0);
            ull a0 = ap[0], a1 = ap[1], a2 = ap[2], a3 = ap[3];
            const float4* bp = (const float4*)(Bs + kk * 128 + n0);
            float4 blo = bp[0], bhi = bp[1];
            float bf[8] = {blo.x, blo.y, blo.z, blo.w, bhi.x, bhi.y, bhi.z, bhi.w};
            #pragma unroll
            for (int j = 0; j < 8; j++) {
                ull b2 = dup2(bf[j]);
                ffma2(acc[0][j], a0, b2);
                ffma2(acc[1][j], a1, b2);
                ffma2(acc[2][j], a2, b2);
                ffma2(acc[3][j], a3, b2);
            }
        }
        __syncthreads();
    }

    unsigned* dstg = (unsigned*)g_XF;
    const size_t plane = (size_t)2048 * 64 * 32 * 4;   // per-split stride in unsigned
    #pragma unroll
    for (int p = 0; p < 4; p++) {
        float lo[8], hi[8];
        #pragma unroll
        for (int j = 0; j < 8; j++) { float2 v = upk(acc[p][j]); lo[j] = v.x; hi[j] = v.y; }
        #pragma unroll
        for (int h = 0; h < 2; h++) {
            float f[8];
            #pragma unroll
            for (int j = 0; j < 8; j++) f[j] = h ? hi[j] : lo[j];
            int m = m0 + 2 * p + h;
            int rr = r0 + m;
            int b6 = rr / 6, s6 = rr - b6 * 6;
            const float4* c4 = (const float4*)(g_C + sslot[m] * Fdim + n0);
            float4 c0 = c4[0], c1 = c4[1];
            float cadd[8] = {c0.x, c0.y, c0.z, c0.w, c1.x, c1.y, c1.z, c1.w};
            #pragma unroll
            for (int j = 0; j < 8; j++) f[j] = fmaxf(f[j] + cadd[j], 0.f);

            int R8 = b6 * 8 + s6;
            int mtB = R8 >> 7;
            int rloc = R8 & 127;
            int mtile = rloc >> 4;
            int rin = rloc & 15;
            int creg = (rin >> 3) + ((nb & 1) << 1);
            int row_off = rin & 7;
            int fb = mtile * 8 + (nb >> 1);
            size_t base = ((((size_t)mtB * 64 + fb) * 32) + row_off * 4) * 4 + creg;
            #pragma unroll
            for (int jp = 0; jp < 4; jp++) {
                float x0 = f[2 * jp], x1 = f[2 * jp + 1];
                unsigned hp = pack2(x0, x1);
                unsigned lp = pack2(x0 - bf16f(x0), x1 - bf16f(x1));
                dstg[base + (size_t)jp * 4] = hp;
                dstg[plane + base + (size_t)jp * 4] = lp;
            }
        }
    }
}

// ---------------- stage 3: bf16 2-split m16n8k16 MMA + min-over-6 + relu out ---------
// D = Ah Bh + Ah Bl + Al Bh  (dropped Al*Bl ~ 2^-16 per product -> ~5e-5 final)
// CTA: M128 x N128 x K128 all smem-resident. grid (4, 2048), x = N-tile.
// Fills are PURE coalesced float4 copies (fragments prebuilt in gmem by producers).
// Epilogue identical to the numerically verified R9/R11 version.
#define KUV_SMEM (131072)
__global__ __launch_bounds__(256, 1) void kuv_mma(const float* __restrict__ gb,
                                                  float* __restrict__ out)
{
    extern __shared__ char dsm[];
    uint4* Ah4 = (uint4*)dsm;                     // 64 fb * 32 * 16B = 32KB
    uint4* Al4 = (uint4*)(dsm + 32768);
    uint2* Bh2 = (uint2*)(dsm + 65536);           // 128 fb * 32 * 8B = 32KB
    uint2* Bl2 = (uint2*)(dsm + 98304);
    int t = threadIdx.x, w = t >> 5, l = t & 31;
    int ntB = blockIdx.x, mtB = blockIdx.y;

    // ---- fills: contiguous vectorized copies ----
    {
        const uint4* sAh = g_XF + (size_t)mtB * 2048;
        const uint4* sAl = g_XF + (size_t)(2048 + mtB) * 2048;
        #pragma unroll
        for (int it = 0; it < 8; it++) {
            int u = t + it * 256;
            Ah4[u] = sAh[u];
            Al4[u] = sAl[u];
        }
        const uint4* sBh = (const uint4*)(g_WF + (size_t)ntB * 4096);
        const uint4* sBl = (const uint4*)(g_WF + (size_t)(16384 + ntB * 4096));
        uint4* dBh = (uint4*)Bh2;
        uint4* dBl = (uint4*)Bl2;
        #pragma unroll
        for (int it = 0; it < 8; it++) {
            int u = t + it * 256;
            dBh[u] = sBh[u];
            dBl[u] = sBl[u];
        }
    }
    __syncthreads();

    // ---- mainloop: 8 k16-steps ----
    int wmFb = (w >> 2) * 32;   // warpM * 4 mtiles * 8 ksteps
    int wnFb = (w & 3) * 32;    // warpN * 4 ntiles * 8 ksteps
    float d[4][4][4];
    #pragma unroll
    for (int mi = 0; mi < 4; mi++)
        #pragma unroll
        for (int ni = 0; ni < 4; ni++)
            #pragma unroll
            for (int r = 0; r < 4; r++) d[mi][ni][r] = 0.f;

    #pragma unroll
    for (int ks = 0; ks < 8; ks++) {
        uint4 ah[4], al[4]; uint2 bh[4], bl[4];
        #pragma unroll
        for (int mi = 0; mi < 4; mi++) {
            ah[mi] = Ah4[(wmFb + mi * 8 + ks) * 32 + l];
            al[mi] = Al4[(wmFb + mi * 8 + ks) * 32 + l];
        }
        #pragma unroll
        for (int ni = 0; ni < 4; ni++) {
            bh[ni] = Bh2[(wnFb + ni * 8 + ks) * 32 + l];
            bl[ni] = Bl2[(wnFb + ni * 8 + ks) * 32 + l];
        }
        #pragma unroll
        for (int mi = 0; mi < 4; mi++)
            #pragma unroll
            for (int ni = 0; ni < 4; ni++) {
                mma_bf16(d[mi][ni], (const unsigned*)&al[mi], (const unsigned*)&bh[ni]);
                mma_bf16(d[mi][ni], (const unsigned*)&ah[mi], (const unsigned*)&bl[ni]);
                mma_bf16(d[mi][ni], (const unsigned*)&ah[mi], (const unsigned*)&bh[ni]);
            }
    }

    // ---- epilogue: mask pad slots, butterfly min over slots, u+v+bias, relu ----
    int slot = l >> 2, c = l & 3;
    if (slot >= 6) {
        #pragma unroll
        for (int mi = 0; mi < 4; mi++)
            #pragma unroll
            for (int ni = 0; ni < 4; ni++)
                #pragma unroll
                for (int r = 0; r < 4; r++) d[mi][ni][r] = 1e30f;
    }
    #pragma unroll
    for (int mi = 0; mi < 4; mi++)
        #pragma unroll
        for (int ni = 0; ni < 4; ni++)
            #pragma unroll
            for (int r = 0; r < 4; r++) {
                float v = d[mi][ni][r];
                v = fminf(v, __shfl_xor_sync(0xFFFFFFFFu, v, 4));
                v = fminf(v, __shfl_xor_sync(0xFFFFFFFFu, v, 8));
                v = fminf(v, __shfl_xor_sync(0xFFFFFFFFu, v, 16));
                d[mi][ni][r] = v;
            }

    int gBase = ntB * 64 + (w & 3) * 16;
    float gbv[4];
    #pragma unroll
    for (int ni = 0; ni < 4; ni++) gbv[ni] = gb[gBase + ni * 4 + c];

    int bbBase = mtB * 16 + (w >> 2) * 8;
    #pragma unroll
    for (int mi = 0; mi < 4; mi++) {
        #pragma unroll
        for (int half = 0; half < 2; half++) {
            int bb = bbBase + mi * 2 + half;
            bool mine = (slot == half * 4 + mi);
            #pragma unroll
            for (int ni = 0; ni < 4; ni++) {
                float uu = d[mi][ni][half * 2 + 0];
                float vv = d[mi][ni][half * 2 + 1];
                float o = fmaxf(uu + vv + gbv[ni], 0.f);
                if (mine) out[(size_t)bb * Gdim + gBase + ni * 4 + c] = o;
            }
        }
    }
}

// ---------------- launcher ----------------
extern "C" void kernel_launch(void* const* d_in, const int* in_sizes, int n_in,
                              void* d_out, int out_size)
{
    const int*   a_ids = (const int*)d_in[0];
    const int*   b_ids = (const int*)d_in[1];
    const int*   c_ids = (const int*)d_in[2];
    const int*   e_ids = (const int*)d_in[3];
    const float* nf    = (const float*)d_in[4];
    const float* cond  = (const float*)d_in[5];
    const float* text  = (const float*)d_in[6];
    const float* ee    = (const float*)d_in[7];
    const float* re    = (const float*)d_in[8];
    const float* nW    = (const float*)d_in[9];
    const float* nbias = (const float*)d_in[10];
    const float* cW    = (const float*)d_in[11];
    const float* cb    = (const float*)d_in[12];
    const float* gam   = (const float*)d_in[13];
    const float* bet   = (const float*)d_in[14];
    const float* mea   = (const float*)d_in[15];
    const float* var   = (const float*)d_in[16];
    const float* gW    = (const float*)d_in[17];
    const float* gbias = (const float*)d_in[18];
    float* out = (float*)d_out;

    cudaFuncSetAttribute(kuv_mma, cudaFuncAttributeMaxDynamicSharedMemorySize, KUV_SMEM);

    kprep<<<7, 128>>>(re, cW, cb, gam, bet, mea, var);
    kprepW<<<128, 256>>>(gW);
    kent<<<(4 * Bsz) / 128, 256>>>(a_ids, e_ids, b_ids, c_ids, nf, ee, nW, nbias);
    kconv<<<(6 * Bsz) / 128, 256>>>(cond, text);
    kuv_mma<<<dim3(4, 2048), 256, KUV_SMEM>>>(gbias, out);
}

// round 15
// speedup vs baseline: 1.8088x; 1.1240x over previous
#include <cuda_runtime.h>
#include <cuda_bf16.h>

#define Bsz   32768
#define Edim  128
#define Fdim  128
#define Gdim  256
#define NFdim 256
#define EPSv  1e-5f

typedef unsigned long long ull;

// ---------------- scratch (device globals: allocation-free; .bss zero-init) ----------
__device__ float g_VALS[(size_t)Bsz * 4 * Edim];     // ent() results, slots 0..3 (64 MB)
// A fragments for stage 3: [split 2][mtB 2048][fb 64][lane 32] uint4  (134 MB)
//   fb = mtile*8 + kst; pad rows (slots 6,7) never written -> stay 0
__device__ uint4 g_XF[(size_t)2 * 2048 * 64 * 32];
// B fragments stage 3: [split 2][ntB 4][fb 128][lane 32] uint2  (256 KB)
__device__ uint2 g_WF[(size_t)2 * 4 * 128 * 32];
// B fragments for kconv_mma (conv weights): [split 2][fb 128][lane 32] uint2 (64 KB)
__device__ uint2 g_WcF[(size_t)2 * 128 * 32];
__device__ float g_C  [6 * Fdim];                    // folded role+bias+BN constant
__device__ float g_WcT[Edim * Fdim];                 // conv_W val-half, transposed, scaled

// ---------------- packed fp32x2 helpers (sm_100+) ----------------
__device__ __forceinline__ void ffma2(ull &d, ull a, ull b){
    asm("fma.rn.f32x2 %0, %1, %2, %0;" : "+l"(d) : "l"(a), "l"(b));
}
__device__ __forceinline__ ull dup2(float x){
    ull r; asm("mov.b64 %0, {%1, %1};" : "=l"(r) : "f"(x)); return r;
}
__device__ __forceinline__ float2 upk(ull v){
    float2 f; asm("mov.b64 {%0, %1}, %2;" : "=f"(f.x), "=f"(f.y) : "l"(v)); return f;
}

// ---------------- bf16 split helpers ----------------
__device__ __forceinline__ float bf16f(float a){
    return __bfloat162float(__float2bfloat16_rn(a));
}
__device__ __forceinline__ unsigned pack2(float a, float b){
    unsigned ua = (unsigned)__bfloat16_as_ushort(__float2bfloat16_rn(a));
    unsigned ub = (unsigned)__bfloat16_as_ushort(__float2bfloat16_rn(b));
    return ua | (ub << 16);
}

// bf16 tensor-core MMA: m16n8k16 (sm_80+)
__device__ __forceinline__ void mma_bf16(float* d, const unsigned* a, const unsigned* b){
    asm volatile(
        "mma.sync.aligned.m16n8k16.row.col.f32.bf16.bf16.f32 "
        "{%0,%1,%2,%3}, {%4,%5,%6,%7}, {%8,%9}, {%0,%1,%2,%3};"
        : "+f"(d[0]), "+f"(d[1]), "+f"(d[2]), "+f"(d[3])
        : "r"(a[0]), "r"(a[1]), "r"(a[2]), "r"(a[3]), "r"(b[0]), "r"(b[1]));
}

// ---------------- prep: fold roles + BN into constants ----------------
__global__ void kprep(const float* __restrict__ role_emb, const float* __restrict__ conv_W,
                      const float* __restrict__ conv_b, const float* __restrict__ gam,
                      const float* __restrict__ bet, const float* __restrict__ mea,
                      const float* __restrict__ var)
{
    int f = threadIdx.x;
    float sc = gam[f] * rsqrtf(var[f] + EPSv);
    int blk = blockIdx.x;
    if (blk < 6) {
        const int roles[6] = {0, 1, 2, 3, 4, 6};
        __shared__ float rs[Edim];
        rs[f] = role_emb[roles[blk] * Edim + f];
        __syncthreads();
        float d = 0.f;
        const float* cw = conv_W + f * 2 * Edim;
        #pragma unroll 8
        for (int e = 0; e < Edim; e++) d += rs[e] * cw[e];
        g_C[blk * Fdim + f] = (d + conv_b[f] - mea[f]) * sc + bet[f];
    } else {
        for (int e = 0; e < Edim; e++)
            g_WcT[e * Fdim + f] = conv_W[f * 2 * Edim + Edim + e] * sc;
    }
}

// conv weights -> bf16-split B fragments (same mapping as verified kprepW)
// B[k=e][n=f] = g_WcT[e*128 + f]; one thread per (n, k-pair p)
__global__ void kprepWc()
{
    int idx = blockIdx.x * 256 + threadIdx.x;   // 0..8191
    int n = idx >> 6, p = idx & 63;
    float v0 = g_WcT[(2 * p) * Fdim + n];
    float v1 = g_WcT[(2 * p + 1) * Fdim + n];
    unsigned hp = pack2(v0, v1);
    unsigned lp = pack2(v0 - bf16f(v0), v1 - bf16f(v1));
    int kst = p >> 3, pi = p & 7, kp = pi & 3, reg = pi >> 2;
    int ntile = n >> 3, lane = (n & 7) * 4 + kp;
    int fb = ntile * 8 + kst;
    unsigned* dst = (unsigned*)g_WcF;
    size_t i0 = ((size_t)fb * 32 + lane) * 2 + reg;
    size_t plane = (size_t)128 * 32 * 2;
    dst[i0] = hp;
    dst[plane + i0] = lp;
}

// prep gfcn_W into B fragments, bf16 2-split. n = 2g+h (h=0 -> W1[k][g], h=1 -> W2).
__global__ void kprepW(const float* __restrict__ gW)
{
    int idx = blockIdx.x * 256 + threadIdx.x;   // 0..32767
    int n = idx >> 6, p = idx & 63;
    int g = n >> 1, h = n & 1;
    float v0 = gW[(size_t)(h * 128 + 2 * p) * Gdim + g];
    float v1 = gW[(size_t)(h * 128 + 2 * p + 1) * Gdim + g];
    unsigned hp = pack2(v0, v1);
    unsigned lp = pack2(v0 - bf16f(v0), v1 - bf16f(v1));
    int kst = p >> 3, pi = p & 7, kp = pi & 3, reg = pi >> 2;
    int ntB = n >> 7, ntile = (n & 127) >> 3, lane = (n & 7) * 4 + kp;
    int fb = ntile * 8 + kst;
    unsigned* dst = (unsigned*)g_WF;
    size_t i0 = (((size_t)ntB * 128 + fb) * 32 + lane) * 2 + reg;
    size_t plane = (size_t)4 * 128 * 32 * 2;
    dst[i0] = hp;
    dst[plane + i0] = lp;
}

// ---------------- stage 1: gathered ent GEMM (FFMA f32x2) ----------------
__global__ __launch_bounds__(256, 2) void kent(
    const int* __restrict__ aid, const int* __restrict__ evid,
    const int* __restrict__ bid, const int* __restrict__ cid,
    const float* __restrict__ nf, const float* __restrict__ ee,
    const float* __restrict__ nW, const float* __restrict__ nbias)
{
    __shared__ int sid[128];
    __shared__ __align__(16) float As[32 * 130];
    __shared__ __align__(16) float Bs[32 * 128];
    int t = threadIdx.x;
    int r0 = blockIdx.x * 128;
    if (t < 128) {
        int R = r0 + t;
        int b = R >> 2, j = R & 3;
        const int* p = (j == 0) ? aid : (j == 1) ? evid : (j == 2) ? bid : cid;
        sid[t] = p[b];
    }
    __syncthreads();
    int mb = t >> 4, nb = t & 15;
    int m0 = mb * 8, n0 = nb * 8;
    ull acc[4][8];
    #pragma unroll
    for (int i = 0; i < 4; i++)
        #pragma unroll
        for (int j = 0; j < 8; j++) acc[i][j] = 0ULL;

    for (int kc = 0; kc < 8; kc++) {
        int k0 = kc * 32;
        #pragma unroll
        for (int it = 0; it < 16; it++) {
            int idx = t + it * 256;
            int m = idx >> 5, k = idx & 31;
            As[k * 130 + m] = nf[(size_t)sid[m] * NFdim + k0 + k];
        }
        {
            const float4* src = (const float4*)(nW + k0 * Fdim);
            float4* dst = (float4*)Bs;
            #pragma unroll
            for (int it = 0; it < 4; it++) dst[t + it * 256] = src[t + it * 256];
        }
        __syncthreads();
        #pragma unroll 4
        for (int kk = 0; kk < 32; kk++) {
            const ull* ap = (const ull*)(As + kk * 130 + m0);
            ull a0 = ap[0], a1 = ap[1], a2 = ap[2], a3 = ap[3];
            const float4* bp = (const float4*)(Bs + kk * 128 + n0);
            float4 blo = bp[0], bhi = bp[1];
            float bf[8] = {blo.x, blo.y, blo.z, blo.w, bhi.x, bhi.y, bhi.z, bhi.w};
            #pragma unroll
            for (int j = 0; j < 8; j++) {
                ull b2 = dup2(bf[j]);
                ffma2(acc[0][j], a0, b2);
                ffma2(acc[1][j], a1, b2);
                ffma2(acc[2][j], a2, b2);
                ffma2(acc[3][j], a3, b2);
            }
        }
        __syncthreads();
    }

    float4 nb0 = *(const float4*)(nbias + n0);
    float4 nb1 = *(const float4*)(nbias + n0 + 4);
    #pragma unroll
    for (int p = 0; p < 4; p++) {
        float lo[8], hi[8];
        #pragma unroll
        for (int j = 0; j < 8; j++) { float2 v = upk(acc[p][j]); lo[j] = v.x; hi[j] = v.y; }
        #pragma unroll
        for (int h = 0; h < 2; h++) {
            float vv[8];
            #pragma unroll
            for (int j = 0; j < 8; j++) vv[j] = h ? hi[j] : lo[j];
            int m = m0 + 2 * p + h;
            int R = r0 + m;
            const float4* e4 = (const float4*)(ee + (size_t)sid[m] * Edim + n0);
            float4 e0 = e4[0], e1 = e4[1];
            float4 o0, o1;
            o0.x = fmaxf(vv[0] + nb0.x, 0.f) + e0.x;
            o0.y = fmaxf(vv[1] + nb0.y, 0.f) + e0.y;
            o0.z = fmaxf(vv[2] + nb0.z, 0.f) + e0.z;
            o0.w = fmaxf(vv[3] + nb0.w, 0.f) + e0.w;
            o1.x = fmaxf(vv[4] + nb1.x, 0.f) + e1.x;
            o1.y = fmaxf(vv[5] + nb1.y, 0.f) + e1.y;
            o1.z = fmaxf(vv[6] + nb1.z, 0.f) + e1.z;
            o1.w = fmaxf(vv[7] + nb1.w, 0.f) + e1.w;
            float4* dst = (float4*)(g_VALS + (size_t)R * Edim + n0);
            dst[0] = o0; dst[1] = o1;
        }
    }
}

// ---------------- stage 2: conv+BN+relu as bf16 2-split MMA, frag-in / frag-out ------
// C[r6][f] = relu( sum_e A[r6][e]*WcT[e][f] + gC[s6][f] ), r6 in 6-slot row space.
// CTA M128 x N128 x K128. Same smem layout / mainloop / warp tiling as kuv_mma.
// Epilogue scatters bf16-split results into g_XF with the R13-verified index math.
#define KCV_SMEM (131072)
__global__ __launch_bounds__(256, 1) void kconv_mma(const float* __restrict__ cond,
                                                    const float* __restrict__ text)
{
    extern __shared__ char dsm[];
    uint4* Ah4 = (uint4*)dsm;                     // 64 fb * 32 * 16B = 32KB
    uint4* Al4 = (uint4*)(dsm + 32768);
    uint2* Bh2 = (uint2*)(dsm + 65536);           // 128 fb * 32 * 8B = 32KB
    uint2* Bl2 = (uint2*)(dsm + 98304);
    __shared__ const float* srcp[128];
    int t = threadIdx.x, w = t >> 5, l = t & 31;
    int mtB = blockIdx.x;
    int r0 = mtB * 128;

    if (t < 128) {
        int r = r0 + t;
        int b = r / 6, s = r - b * 6;
        const float* p;
        if (s < 4)       p = g_VALS + ((size_t)b * 4 + s) * Edim;
        else if (s == 4) p = cond + (size_t)b * Edim;
        else             p = text + (size_t)b * Edim;
        srcp[t] = p;
    }
    // B fill: plain copies of precomputed fragments
    {
        const uint4* sBh = (const uint4*)g_WcF;
        const uint4* sBl = ((const uint4*)g_WcF) + 2048;   // +32KB
        uint4* dBh = (uint4*)Bh2;
        uint4* dBl = (uint4*)Bl2;
        #pragma unroll
        for (int it = 0; it < 8; it++) {
            int u = t + it * 256;
            dBh[u] = sBh[u];
            dBl[u] = sBl[u];
        }
    }
    __syncthreads();   // srcp ready
    // A fill: gather rows, convert fp32 -> bf16 hi/lo fragment pairs
    {
        unsigned* AhU = (unsigned*)Ah4;
        unsigned* AlU = (unsigned*)Al4;
        #pragma unroll
        for (int it = 0; it < 16; it++) {
            int u = t + it * 256;                 // 0..4095: (row, k-quad)
            int row = u >> 5, kq = (u & 31) << 2;
            float4 v = *(const float4*)(srcp[row] + kq);
            int mtile = row >> 4, rin = row & 15;
            int kst = kq >> 4, klocal = kq & 15;
            int reg = (rin >> 3) + ((klocal >> 3) << 1);
            int lane = (rin & 7) * 4 + ((klocal & 7) >> 1);
            int base = ((mtile * 8 + kst) * 32 + lane) * 4 + reg;
            AhU[base]     = pack2(v.x, v.y);
            AhU[base + 4] = pack2(v.z, v.w);
            AlU[base]     = pack2(v.x - bf16f(v.x), v.y - bf16f(v.y));
            AlU[base + 4] = pack2(v.z - bf16f(v.z), v.w - bf16f(v.w));
        }
    }
    __syncthreads();

    // ---- mainloop: identical to kuv_mma ----
    int wmFb = (w >> 2) * 32;
    int wnFb = (w & 3) * 32;
    float d[4][4][4];
    #pragma unroll
    for (int mi = 0; mi < 4; mi++)
        #pragma unroll
        for (int ni = 0; ni < 4; ni++)
            #pragma unroll
            for (int r = 0; r < 4; r++) d[mi][ni][r] = 0.f;

    #pragma unroll
    for (int ks = 0; ks < 8; ks++) {
        uint4 ah[4], al[4]; uint2 bh[4], bl[4];
        #pragma unroll
        for (int mi = 0; mi < 4; mi++) {
            ah[mi] = Ah4[(wmFb + mi * 8 + ks) * 32 + l];
            al[mi] = Al4[(wmFb + mi * 8 + ks) * 32 + l];
        }
        #pragma unroll
        for (int ni = 0; ni < 4; ni++) {
            bh[ni] = Bh2[(wnFb + ni * 8 + ks) * 32 + l];
            bl[ni] = Bl2[(wnFb + ni * 8 + ks) * 32 + l];
        }
        #pragma unroll
        for (int mi = 0; mi < 4; mi++)
            #pragma unroll
            for (int ni = 0; ni < 4; ni++) {
                mma_bf16(d[mi][ni], (const unsigned*)&al[mi], (const unsigned*)&bh[ni]);
                mma_bf16(d[mi][ni], (const unsigned*)&ah[mi], (const unsigned*)&bl[ni]);
                mma_bf16(d[mi][ni], (const unsigned*)&ah[mi], (const unsigned*)&bh[ni]);
            }
    }

    // ---- epilogue: +C, relu, bf16-split, scatter to g_XF (verified index math) ----
    int mrowBase = (w >> 2) * 64 + (l >> 2);
    int fBase = (w & 3) * 32 + (l & 3) * 2;
    unsigned* dstg = (unsigned*)g_XF;
    const size_t plane = (size_t)2048 * 64 * 32 * 4;   // per-split stride in unsigned
    #pragma unroll
    for (int mi = 0; mi < 4; mi++) {
        #pragma unroll
        for (int rh = 0; rh < 2; rh++) {
            int R6 = r0 + mrowBase + mi * 16 + rh * 8;
            int b6 = R6 / 6, s6 = R6 - b6 * 6;
            int R8 = b6 * 8 + s6;
            int omtB = R8 >> 7, orloc = R8 & 127;
            int omtile = orloc >> 4, orin = orloc & 15;
            int ocreg0 = orin >> 3;
            int olanebase = (orin & 7) * 4;
            #pragma unroll
            for (int ni = 0; ni < 4; ni++) {
                int f0 = fBase + ni * 8;
                float2 cc = *(const float2*)(g_C + s6 * Fdim + f0);
                float v0 = fmaxf(d[mi][ni][rh * 2 + 0] + cc.x, 0.f);
                float v1 = fmaxf(d[mi][ni][rh * 2 + 1] + cc.y, 0.f);
                int okst = f0 >> 4, okl = f0 & 15;
                int ocreg = ocreg0 + ((okl >> 3) << 1);
                int olane = olanebase + ((okl & 7) >> 1);
                size_t idx = (((size_t)omtB * 64 + omtile * 8 + okst) * 32 + olane) * 4
                           + ocreg;
                dstg[idx] = pack2(v0, v1);
                dstg[plane + idx] = pack2(v0 - bf16f(v0), v1 - bf16f(v1));
            }
        }
    }
}

// ---------------- stage 3: bf16 2-split m16n8k16 MMA + min-over-6 + relu out ---------
#define KUV_SMEM (131072)
__global__ __launch_bounds__(256, 1) void kuv_mma(const float* __restrict__ gb,
                                                  float* __restrict__ out)
{
    extern __shared__ char dsm[];
    uint4* Ah4 = (uint4*)dsm;                     // 64 fb * 32 * 16B = 32KB
    uint4* Al4 = (uint4*)(dsm + 32768);
    uint2* Bh2 = (uint2*)(dsm + 65536);           // 128 fb * 32 * 8B = 32KB
    uint2* Bl2 = (uint2*)(dsm + 98304);
    int t = threadIdx.x, w = t >> 5, l = t & 31;
    int ntB = blockIdx.x, mtB = blockIdx.y;

    // ---- fills: contiguous vectorized copies ----
    {
        const uint4* sAh = g_XF + (size_t)mtB * 2048;
        const uint4* sAl = g_XF + (size_t)(2048 + mtB) * 2048;
        #pragma unroll
        for (int it = 0; it < 8; it++) {
            int u = t + it * 256;
            Ah4[u] = sAh[u];
            Al4[u] = sAl[u];
        }
        const uint4* sBh = (const uint4*)(g_WF + (size_t)ntB * 4096);
        const uint4* sBl = (const uint4*)(g_WF + (size_t)(16384 + ntB * 4096));
        uint4* dBh = (uint4*)Bh2;
        uint4* dBl = (uint4*)Bl2;
        #pragma unroll
        for (int it = 0; it < 8; it++) {
            int u = t + it * 256;
            dBh[u] = sBh[u];
            dBl[u] = sBl[u];
        }
    }
    __syncthreads();

    // ---- mainloop: 8 k16-steps ----
    int wmFb = (w >> 2) * 32;
    int wnFb = (w & 3) * 32;
    float d[4][4][4];
    #pragma unroll
    for (int mi = 0; mi < 4; mi++)
        #pragma unroll
        for (int ni = 0; ni < 4; ni++)
            #pragma unroll
            for (int r = 0; r < 4; r++) d[mi][ni][r] = 0.f;

    #pragma unroll
    for (int ks = 0; ks < 8; ks++) {
        uint4 ah[4], al[4]; uint2 bh[4], bl[4];
        #pragma unroll
        for (int mi = 0; mi < 4; mi++) {
            ah[mi] = Ah4[(wmFb + mi * 8 + ks) * 32 + l];
            al[mi] = Al4[(wmFb + mi * 8 + ks) * 32 + l];
        }
        #pragma unroll
        for (int ni = 0; ni < 4; ni++) {
            bh[ni] = Bh2[(wnFb + ni * 8 + ks) * 32 + l];
            bl[ni] = Bl2[(wnFb + ni * 8 + ks) * 32 + l];
        }
        #pragma unroll
        for (int mi = 0; mi < 4; mi++)
            #pragma unroll
            for (int ni = 0; ni < 4; ni++) {
                mma_bf16(d[mi][ni], (const unsigned*)&al[mi], (const unsigned*)&bh[ni]);
                mma_bf16(d[mi][ni], (const unsigned*)&ah[mi], (const unsigned*)&bl[ni]);
                mma_bf16(d[mi][ni], (const unsigned*)&ah[mi], (const unsigned*)&bh[ni]);
            }
    }

    // ---- epilogue: mask pad slots, butterfly min over slots, u+v+bias, relu ----
    int slot = l >> 2, c = l & 3;
    if (slot >= 6) {
        #pragma unroll
        for (int mi = 0; mi < 4; mi++)
            #pragma unroll
            for (int ni = 0; ni < 4; ni++)
                #pragma unroll
                for (int r = 0; r < 4; r++) d[mi][ni][r] = 1e30f;
    }
    #pragma unroll
    for (int mi = 0; mi < 4; mi++)
        #pragma unroll
        for (int ni = 0; ni < 4; ni++)
            #pragma unroll
            for (int r = 0; r < 4; r++) {
                float v = d[mi][ni][r];
                v = fminf(v, __shfl_xor_sync(0xFFFFFFFFu, v, 4));
                v = fminf(v, __shfl_xor_sync(0xFFFFFFFFu, v, 8));
                v = fminf(v, __shfl_xor_sync(0xFFFFFFFFu, v, 16));
                d[mi][ni][r] = v;
            }

    int gBase = ntB * 64 + (w & 3) * 16;
    float gbv[4];
    #pragma unroll
    for (int ni = 0; ni < 4; ni++) gbv[ni] = gb[gBase + ni * 4 + c];

    int bbBase = mtB * 16 + (w >> 2) * 8;
    #pragma unroll
    for (int mi = 0; mi < 4; mi++) {
        #pragma unroll
        for (int half = 0; half < 2; half++) {
            int bb = bbBase + mi * 2 + half;
            bool mine = (slot == half * 4 + mi);
            #pragma unroll
            for (int ni = 0; ni < 4; ni++) {
                float uu = d[mi][ni][half * 2 + 0];
                float vv = d[mi][ni][half * 2 + 1];
                float o = fmaxf(uu + vv + gbv[ni], 0.f);
                if (mine) out[(size_t)bb * Gdim + gBase + ni * 4 + c] = o;
            }
        }
    }
}

// ---------------- launcher ----------------
extern "C" void kernel_launch(void* const* d_in, const int* in_sizes, int n_in,
                              void* d_out, int out_size)
{
    const int*   a_ids = (const int*)d_in[0];
    const int*   b_ids = (const int*)d_in[1];
    const int*   c_ids = (const int*)d_in[2];
    const int*   e_ids = (const int*)d_in[3];
    const float* nf    = (const float*)d_in[4];
    const float* cond  = (const float*)d_in[5];
    const float* text  = (const float*)d_in[6];
    const float* ee    = (const float*)d_in[7];
    const float* re    = (const float*)d_in[8];
    const float* nW    = (const float*)d_in[9];
    const float* nbias = (const float*)d_in[10];
    const float* cW    = (const float*)d_in[11];
    const float* cb    = (const float*)d_in[12];
    const float* gam   = (const float*)d_in[13];
    const float* bet   = (const float*)d_in[14];
    const float* mea   = (const float*)d_in[15];
    const float* var   = (const float*)d_in[16];
    const float* gW    = (const float*)d_in[17];
    const float* gbias = (const float*)d_in[18];
    float* out = (float*)d_out;

    cudaFuncSetAttribute(kuv_mma, cudaFuncAttributeMaxDynamicSharedMemorySize, KUV_SMEM);
    cudaFuncSetAttribute(kconv_mma, cudaFuncAttributeMaxDynamicSharedMemorySize, KCV_SMEM);

    kprep<<<7, 128>>>(re, cW, cb, gam, bet, mea, var);
    kprepWc<<<32, 256>>>();
    kprepW<<<128, 256>>>(gW);
    kent<<<(4 * Bsz) / 128, 256>>>(a_ids, e_ids, b_ids, c_ids, nf, ee, nW, nbias);
    kconv_mma<<<(6 * Bsz) / 128, 256, KCV_SMEM>>>(cond, text);
    kuv_mma<<<dim3(4, 2048), 256, KUV_SMEM>>>(gbias, out);
}

// round 16
// speedup vs baseline: 1.8299x; 1.0116x over previous
#include <cuda_runtime.h>
#include <cuda_bf16.h>

#define Bsz   32768
#define Edim  128
#define Fdim  128
#define Gdim  256
#define NFdim 256
#define EPSv  1e-5f

typedef unsigned long long ull;

// ---------------- scratch (device globals: allocation-free; .bss zero-init) ----------
__device__ float g_VALS[(size_t)Bsz * 4 * Edim];     // ent() results, slots 0..3 (64 MB)
// A fragments for stage 3: [split 2][mtB 2048][fb 64][lane 32] uint4  (134 MB)
//   fb = mtile*8 + kst; pad rows (slots 6,7) never written -> stay 0
__device__ uint4 g_XF[(size_t)2 * 2048 * 64 * 32];
// B fragments stage 3: [split 2][ntB 4][fb 128][lane 32] uint2  (256 KB)
__device__ uint2 g_WF[(size_t)2 * 4 * 128 * 32];
// B fragments for kconv_mma (conv weights): [split 2][fb 128][lane 32] uint2 (64 KB)
__device__ uint2 g_WcF[(size_t)2 * 128 * 32];
__device__ float g_C  [6 * Fdim];                    // folded role+bias+BN constant
__device__ float g_WcT[Edim * Fdim];                 // conv_W val-half, transposed, scaled

// ---------------- packed fp32x2 helpers (sm_100+) ----------------
__device__ __forceinline__ void ffma2(ull &d, ull a, ull b){
    asm("fma.rn.f32x2 %0, %1, %2, %0;" : "+l"(d) : "l"(a), "l"(b));
}
__device__ __forceinline__ ull dup2(float x){
    ull r; asm("mov.b64 %0, {%1, %1};" : "=l"(r) : "f"(x)); return r;
}
__device__ __forceinline__ float2 upk(ull v){
    float2 f; asm("mov.b64 {%0, %1}, %2;" : "=f"(f.x), "=f"(f.y) : "l"(v)); return f;
}

// ---------------- bf16 split helpers ----------------
__device__ __forceinline__ float bf16f(float a){
    return __bfloat162float(__float2bfloat16_rn(a));
}
__device__ __forceinline__ unsigned pack2(float a, float b){
    unsigned ua = (unsigned)__bfloat16_as_ushort(__float2bfloat16_rn(a));
    unsigned ub = (unsigned)__bfloat16_as_ushort(__float2bfloat16_rn(b));
    return ua | (ub << 16);
}

// bf16 tensor-core MMA: m16n8k16 (sm_80+)
__device__ __forceinline__ void mma_bf16(float* d, const unsigned* a, const unsigned* b){
    asm volatile(
        "mma.sync.aligned.m16n8k16.row.col.f32.bf16.bf16.f32 "
        "{%0,%1,%2,%3}, {%4,%5,%6,%7}, {%8,%9}, {%0,%1,%2,%3};"
        : "+f"(d[0]), "+f"(d[1]), "+f"(d[2]), "+f"(d[3])
        : "r"(a[0]), "r"(a[1]), "r"(a[2]), "r"(a[3]), "r"(b[0]), "r"(b[1]));
}

// ---------------- prep: fold roles + BN into constants ----------------
__global__ void kprep(const float* __restrict__ role_emb, const float* __restrict__ conv_W,
                      const float* __restrict__ conv_b, const float* __restrict__ gam,
                      const float* __restrict__ bet, const float* __restrict__ mea,
                      const float* __restrict__ var)
{
    int f = threadIdx.x;
    float sc = gam[f] * rsqrtf(var[f] + EPSv);
    int blk = blockIdx.x;
    if (blk < 6) {
        const int roles[6] = {0, 1, 2, 3, 4, 6};
        __shared__ float rs[Edim];
        rs[f] = role_emb[roles[blk] * Edim + f];
        __syncthreads();
        float d = 0.f;
        const float* cw = conv_W + f * 2 * Edim;
        #pragma unroll 8
        for (int e = 0; e < Edim; e++) d += rs[e] * cw[e];
        g_C[blk * Fdim + f] = (d + conv_b[f] - mea[f]) * sc + bet[f];
    } else {
        for (int e = 0; e < Edim; e++)
            g_WcT[e * Fdim + f] = conv_W[f * 2 * Edim + Edim + e] * sc;
    }
}

// conv weights -> bf16-split B fragments (same mapping as verified kprepW)
// B[k=e][n=f] = g_WcT[e*128 + f]; one thread per (n, k-pair p)
__global__ void kprepWc()
{
    int idx = blockIdx.x * 256 + threadIdx.x;   // 0..8191
    int n = idx >> 6, p = idx & 63;
    float v0 = g_WcT[(2 * p) * Fdim + n];
    float v1 = g_WcT[(2 * p + 1) * Fdim + n];
    unsigned hp = pack2(v0, v1);
    unsigned lp = pack2(v0 - bf16f(v0), v1 - bf16f(v1));
    int kst = p >> 3, pi = p & 7, kp = pi & 3, reg = pi >> 2;
    int ntile = n >> 3, lane = (n & 7) * 4 + kp;
    int fb = ntile * 8 + kst;
    unsigned* dst = (unsigned*)g_WcF;
    size_t i0 = ((size_t)fb * 32 + lane) * 2 + reg;
    size_t plane = (size_t)128 * 32 * 2;
    dst[i0] = hp;
    dst[plane + i0] = lp;
}

// prep gfcn_W into B fragments, bf16 2-split. n = 2g+h (h=0 -> W1[k][g], h=1 -> W2).
__global__ void kprepW(const float* __restrict__ gW)
{
    int idx = blockIdx.x * 256 + threadIdx.x;   // 0..32767
    int n = idx >> 6, p = idx & 63;
    int g = n >> 1, h = n & 1;
    float v0 = gW[(size_t)(h * 128 + 2 * p) * Gdim + g];
    float v1 = gW[(size_t)(h * 128 + 2 * p + 1) * Gdim + g];
    unsigned hp = pack2(v0, v1);
    unsigned lp = pack2(v0 - bf16f(v0), v1 - bf16f(v1));
    int kst = p >> 3, pi = p & 7, kp = pi & 3, reg = pi >> 2;
    int ntB = n >> 7, ntile = (n & 127) >> 3, lane = (n & 7) * 4 + kp;
    int fb = ntile * 8 + kst;
    unsigned* dst = (unsigned*)g_WF;
    size_t i0 = (((size_t)ntB * 128 + fb) * 32 + lane) * 2 + reg;
    size_t plane = (size_t)4 * 128 * 32 * 2;
    dst[i0] = hp;
    dst[plane + i0] = lp;
}

// ---------------- stage 1: gathered ent GEMM (FFMA f32x2) ----------------
__global__ __launch_bounds__(256, 2) void kent(
    const int* __restrict__ aid, const int* __restrict__ evid,
    const int* __restrict__ bid, const int* __restrict__ cid,
    const float* __restrict__ nf, const float* __restrict__ ee,
    const float* __restrict__ nW, const float* __restrict__ nbias)
{
    __shared__ int sid[128];
    __shared__ __align__(16) float As[32 * 130];
    __shared__ __align__(16) float Bs[32 * 128];
    int t = threadIdx.x;
    int r0 = blockIdx.x * 128;
    if (t < 128) {
        int R = r0 + t;
        int b = R >> 2, j = R & 3;
        const int* p = (j == 0) ? aid : (j == 1) ? evid : (j == 2) ? bid : cid;
        sid[t] = p[b];
    }
    __syncthreads();
    int mb = t >> 4, nb = t & 15;
    int m0 = mb * 8, n0 = nb * 8;
    ull acc[4][8];
    #pragma unroll
    for (int i = 0; i < 4; i++)
        #pragma unroll
        for (int j = 0; j < 8; j++) acc[i][j] = 0ULL;

    for (int kc = 0; kc < 8; kc++) {
        int k0 = kc * 32;
        #pragma unroll
        for (int it = 0; it < 16; it++) {
            int idx = t + it * 256;
            int m = idx >> 5, k = idx & 31;
            As[k * 130 + m] = nf[(size_t)sid[m] * NFdim + k0 + k];
        }
        {
            const float4* src = (const float4*)(nW + k0 * Fdim);
            float4* dst = (float4*)Bs;
            #pragma unroll
            for (int it = 0; it < 4; it++) dst[t + it * 256] = src[t + it * 256];
        }
        __syncthreads();
        #pragma unroll 4
        for (int kk = 0; kk < 32; kk++) {
            const ull* ap = (const ull*)(As + kk * 130 + m0);
            ull a0 = ap[0], a1 = ap[1], a2 = ap[2], a3 = ap[3];
            const float4* bp = (const float4*)(Bs + kk * 128 + n0);
            float4 blo = bp[0], bhi = bp[1];
            float bf[8] = {blo.x, blo.y, blo.z, blo.w, bhi.x, bhi.y, bhi.z, bhi.w};
            #pragma unroll
            for (int j = 0; j < 8; j++) {
                ull b2 = dup2(bf[j]);
                ffma2(acc[0][j], a0, b2);
                ffma2(acc[1][j], a1, b2);
                ffma2(acc[2][j], a2, b2);
                ffma2(acc[3][j], a3, b2);
            }
        }
        __syncthreads();
    }

    float4 nb0 = *(const float4*)(nbias + n0);
    float4 nb1 = *(const float4*)(nbias + n0 + 4);
    #pragma unroll
    for (int p = 0; p < 4; p++) {
        float lo[8], hi[8];
        #pragma unroll
        for (int j = 0; j < 8; j++) { float2 v = upk(acc[p][j]); lo[j] = v.x; hi[j] = v.y; }
        #pragma unroll
        for (int h = 0; h < 2; h++) {
            float vv[8];
            #pragma unroll
            for (int j = 0; j < 8; j++) vv[j] = h ? hi[j] : lo[j];
            int m = m0 + 2 * p + h;
            int R = r0 + m;
            const float4* e4 = (const float4*)(ee + (size_t)sid[m] * Edim + n0);
            float4 e0 = e4[0], e1 = e4[1];
            float4 o0, o1;
            o0.x = fmaxf(vv[0] + nb0.x, 0.f) + e0.x;
            o0.y = fmaxf(vv[1] + nb0.y, 0.f) + e0.y;
            o0.z = fmaxf(vv[2] + nb0.z, 0.f) + e0.z;
            o0.w = fmaxf(vv[3] + nb0.w, 0.f) + e0.w;
            o1.x = fmaxf(vv[4] + nb1.x, 0.f) + e1.x;
            o1.y = fmaxf(vv[5] + nb1.y, 0.f) + e1.y;
            o1.z = fmaxf(vv[6] + nb1.z, 0.f) + e1.z;
            o1.w = fmaxf(vv[7] + nb1.w, 0.f) + e1.w;
            float4* dst = (float4*)(g_VALS + (size_t)R * Edim + n0);
            dst[0] = o0; dst[1] = o1;
        }
    }
}

// ---------------- stage 2: conv+BN+relu as bf16 2-split MMA, frag-in / frag-out ------
// C[r6][f] = relu( sum_e A[r6][e]*WcT[e][f] + gC[s6][f] ), r6 in 6-slot row space.
// CTA M128 x N128 x K128. Same smem layout / mainloop / warp tiling as kuv_mma.
// Epilogue scatters bf16-split results into g_XF with the R13-verified index math.
#define KCV_SMEM (131072)
__global__ __launch_bounds__(256, 1) void kconv_mma(const float* __restrict__ cond,
                                                    const float* __restrict__ text)
{
    extern __shared__ char dsm[];
    uint4* Ah4 = (uint4*)dsm;                     // 64 fb * 32 * 16B = 32KB
    uint4* Al4 = (uint4*)(dsm + 32768);
    uint2* Bh2 = (uint2*)(dsm + 65536);           // 128 fb * 32 * 8B = 32KB
    uint2* Bl2 = (uint2*)(dsm + 98304);
    __shared__ const float* srcp[128];
    int t = threadIdx.x, w = t >> 5, l = t & 31;
    int mtB = blockIdx.x;
    int r0 = mtB * 128;

    if (t < 128) {
        int r = r0 + t;
        int b = r / 6, s = r - b * 6;
        const float* p;
        if (s < 4)       p = g_VALS + ((size_t)b * 4 + s) * Edim;
        else if (s == 4) p = cond + (size_t)b * Edim;
        else             p = text + (size_t)b * Edim;
        srcp[t] = p;
    }
    // B fill: plain copies of precomputed fragments
    {
        const uint4* sBh = (const uint4*)g_WcF;
        const uint4* sBl = ((const uint4*)g_WcF) + 2048;   // +32KB
        uint4* dBh = (uint4*)Bh2;
        uint4* dBl = (uint4*)Bl2;
        #pragma unroll
        for (int it = 0; it < 8; it++) {
            int u = t + it * 256;
            dBh[u] = sBh[u];
            dBl[u] = sBl[u];
        }
    }
    __syncthreads();   // srcp ready
    // A fill: gather rows, convert fp32 -> bf16 hi/lo fragment pairs
    {
        unsigned* AhU = (unsigned*)Ah4;
        unsigned* AlU = (unsigned*)Al4;
        #pragma unroll
        for (int it = 0; it < 16; it++) {
            int u = t + it * 256;                 // 0..4095: (row, k-quad)
            int row = u >> 5, kq = (u & 31) << 2;
            float4 v = *(const float4*)(srcp[row] + kq);
            int mtile = row >> 4, rin = row & 15;
            int kst = kq >> 4, klocal = kq & 15;
            int reg = (rin >> 3) + ((klocal >> 3) << 1);
            int lane = (rin & 7) * 4 + ((klocal & 7) >> 1);
            int base = ((mtile * 8 + kst) * 32 + lane) * 4 + reg;
            AhU[base]     = pack2(v.x, v.y);
            AhU[base + 4] = pack2(v.z, v.w);
            AlU[base]     = pack2(v.x - bf16f(v.x), v.y - bf16f(v.y));
            AlU[base + 4] = pack2(v.z - bf16f(v.z), v.w - bf16f(v.w));
        }
    }
    __syncthreads();

    // ---- mainloop: identical to kuv_mma ----
    int wmFb = (w >> 2) * 32;
    int wnFb = (w & 3) * 32;
    float d[4][4][4];
    #pragma unroll
    for (int mi = 0; mi < 4; mi++)
        #pragma unroll
        for (int ni = 0; ni < 4; ni++)
            #pragma unroll
            for (int r = 0; r < 4; r++) d[mi][ni][r] = 0.f;

    #pragma unroll
    for (int ks = 0; ks < 8; ks++) {
        uint4 ah[4], al[4]; uint2 bh[4], bl[4];
        #pragma unroll
        for (int mi = 0; mi < 4; mi++) {
            ah[mi] = Ah4[(wmFb + mi * 8 + ks) * 32 + l];
            al[mi] = Al4[(wmFb + mi * 8 + ks) * 32 + l];
        }
        #pragma unroll
        for (int ni = 0; ni < 4; ni++) {
            bh[ni] = Bh2[(wnFb + ni * 8 + ks) * 32 + l];
            bl[ni] = Bl2[(wnFb + ni * 8 + ks) * 32 + l];
        }
        #pragma unroll
        for (int mi = 0; mi < 4; mi++)
            #pragma unroll
            for (int ni = 0; ni < 4; ni++) {
                mma_bf16(d[mi][ni], (const unsigned*)&al[mi], (const unsigned*)&bh[ni]);
                mma_bf16(d[mi][ni], (const unsigned*)&ah[mi], (const unsigned*)&bl[ni]);
                mma_bf16(d[mi][ni], (const unsigned*)&ah[mi], (const unsigned*)&bh[ni]);
            }
    }

    // ---- epilogue: +C, relu, bf16-split, scatter to g_XF (verified index math) ----
    int mrowBase = (w >> 2) * 64 + (l >> 2);
    int fBase = (w & 3) * 32 + (l & 3) * 2;
    unsigned* dstg = (unsigned*)g_XF;
    const size_t plane = (size_t)2048 * 64 * 32 * 4;   // per-split stride in unsigned
    #pragma unroll
    for (int mi = 0; mi < 4; mi++) {
        #pragma unroll
        for (int rh = 0; rh < 2; rh++) {
            int R6 = r0 + mrowBase + mi * 16 + rh * 8;
            int b6 = R6 / 6, s6 = R6 - b6 * 6;
            int R8 = b6 * 8 + s6;
            int omtB = R8 >> 7, orloc = R8 & 127;
            int omtile = orloc >> 4, orin = orloc & 15;
            int ocreg0 = orin >> 3;
            int olanebase = (orin & 7) * 4;
            #pragma unroll
            for (int ni = 0; ni < 4; ni++) {
                int f0 = fBase + ni * 8;
                float2 cc = *(const float2*)(g_C + s6 * Fdim + f0);
                float v0 = fmaxf(d[mi][ni][rh * 2 + 0] + cc.x, 0.f);
                float v1 = fmaxf(d[mi][ni][rh * 2 + 1] + cc.y, 0.f);
                int okst = f0 >> 4, okl = f0 & 15;
                int ocreg = ocreg0 + ((okl >> 3) << 1);
                int olane = olanebase + ((okl & 7) >> 1);
                size_t idx = (((size_t)omtB * 64 + omtile * 8 + okst) * 32 + olane) * 4
                           + ocreg;
                dstg[idx] = pack2(v0, v1);
                dstg[plane + idx] = pack2(v0 - bf16f(v0), v1 - bf16f(v1));
            }
        }
    }
}

// ---------------- stage 3: bf16 2-split m16n8k16 MMA + min-over-6 + relu out ---------
#define KUV_SMEM (131072)
__global__ __launch_bounds__(256, 1) void kuv_mma(const float* __restrict__ gb,
                                                  float* __restrict__ out)
{
    extern __shared__ char dsm[];
    uint4* Ah4 = (uint4*)dsm;                     // 64 fb * 32 * 16B = 32KB
    uint4* Al4 = (uint4*)(dsm + 32768);
    uint2* Bh2 = (uint2*)(dsm + 65536);           // 128 fb * 32 * 8B = 32KB
    uint2* Bl2 = (uint2*)(dsm + 98304);
    int t = threadIdx.x, w = t >> 5, l = t & 31;
    int ntB = blockIdx.x, mtB = blockIdx.y;

    // ---- fills: contiguous vectorized copies ----
    {
        const uint4* sAh = g_XF + (size_t)mtB * 2048;
        const uint4* sAl = g_XF + (size_t)(2048 + mtB) * 2048;
        #pragma unroll
        for (int it = 0; it < 8; it++) {
            int u = t + it * 256;
            Ah4[u] = sAh[u];
            Al4[u] = sAl[u];
        }
        const uint4* sBh = (const uint4*)(g_WF + (size_t)ntB * 4096);
        const uint4* sBl = (const uint4*)(g_WF + (size_t)(16384 + ntB * 4096));
        uint4* dBh = (uint4*)Bh2;
        uint4* dBl = (uint4*)Bl2;
        #pragma unroll
        for (int it = 0; it < 8; it++) {
            int u = t + it * 256;
            dBh[u] = sBh[u];
            dBl[u] = sBl[u];
        }
    }
    __syncthreads();

    // ---- mainloop: 8 k16-steps ----
    int wmFb = (w >> 2) * 32;
    int wnFb = (w & 3) * 32;
    float d[4][4][4];
    #pragma unroll
    for (int mi = 0; mi < 4; mi++)
        #pragma unroll
        for (int ni = 0; ni < 4; ni++)
            #pragma unroll
            for (int r = 0; r < 4; r++) d[mi][ni][r] = 0.f;

    #pragma unroll
    for (int ks = 0; ks < 8; ks++) {
        uint4 ah[4], al[4]; uint2 bh[4], bl[4];
        #pragma unroll
        for (int mi = 0; mi < 4; mi++) {
            ah[mi] = Ah4[(wmFb + mi * 8 + ks) * 32 + l];
            al[mi] = Al4[(wmFb + mi * 8 + ks) * 32 + l];
        }
        #pragma unroll
        for (int ni = 0; ni < 4; ni++) {
            bh[ni] = Bh2[(wnFb + ni * 8 + ks) * 32 + l];
            bl[ni] = Bl2[(wnFb + ni * 8 + ks) * 32 + l];
        }
        #pragma unroll
        for (int mi = 0; mi < 4; mi++)
            #pragma unroll
            for (int ni = 0; ni < 4; ni++) {
                mma_bf16(d[mi][ni], (const unsigned*)&al[mi], (const unsigned*)&bh[ni]);
                mma_bf16(d[mi][ni], (const unsigned*)&ah[mi], (const unsigned*)&bl[ni]);
                mma_bf16(d[mi][ni], (const unsigned*)&ah[mi], (const unsigned*)&bh[ni]);
            }
    }

    // ---- epilogue: mask pad slots, butterfly min over slots, u+v+bias, relu ----
    int slot = l >> 2, c = l & 3;
    if (slot >= 6) {
        #pragma unroll
        for (int mi = 0; mi < 4; mi++)
            #pragma unroll
            for (int ni = 0; ni < 4; ni++)
                #pragma unroll
                for (int r = 0; r < 4; r++) d[mi][ni][r] = 1e30f;
    }
    #pragma unroll
    for (int mi = 0; mi < 4; mi++)
        #pragma unroll
        for (int ni = 0; ni < 4; ni++)
            #pragma unroll
            for (int r = 0; r < 4; r++) {
                float v = d[mi][ni][r];
                v = fminf(v, __shfl_xor_sync(0xFFFFFFFFu, v, 4));
                v = fminf(v, __shfl_xor_sync(0xFFFFFFFFu, v, 8));
                v = fminf(v, __shfl_xor_sync(0xFFFFFFFFu, v, 16));
                d[mi][ni][r] = v;
            }

    int gBase = ntB * 64 + (w & 3) * 16;
    float gbv[4];
    #pragma unroll
    for (int ni = 0; ni < 4; ni++) gbv[ni] = gb[gBase + ni * 4 + c];

    int bbBase = mtB * 16 + (w >> 2) * 8;
    #pragma unroll
    for (int mi = 0; mi < 4; mi++) {
        #pragma unroll
        for (int half = 0; half < 2; half++) {
            int bb = bbBase + mi * 2 + half;
            bool mine = (slot == half * 4 + mi);
            #pragma unroll
            for (int ni = 0; ni < 4; ni++) {
                float uu = d[mi][ni][half * 2 + 0];
                float vv = d[mi][ni][half * 2 + 1];
                float o = fmaxf(uu + vv + gbv[ni], 0.f);
                if (mine) out[(size_t)bb * Gdim + gBase + ni * 4 + c] = o;
            }
        }
    }
}

// ---------------- launcher ----------------
extern "C" void kernel_launch(void* const* d_in, const int* in_sizes, int n_in,
                              void* d_out, int out_size)
{
    const int*   a_ids = (const int*)d_in[0];
    const int*   b_ids = (const int*)d_in[1];
    const int*   c_ids = (const int*)d_in[2];
    const int*   e_ids = (const int*)d_in[3];
    const float* nf    = (const float*)d_in[4];
    const float* cond  = (const float*)d_in[5];
    const float* text  = (const float*)d_in[6];
    const float* ee    = (const float*)d_in[7];
    const float* re    = (const float*)d_in[8];
    const float* nW    = (const float*)d_in[9];
    const float* nbias = (const float*)d_in[10];
    const float* cW    = (const float*)d_in[11];
    const float* cb    = (const float*)d_in[12];
    const float* gam   = (const float*)d_in[13];
    const float* bet   = (const float*)d_in[14];
    const float* mea   = (const float*)d_in[15];
    const float* var   = (const float*)d_in[16];
    const float* gW    = (const float*)d_in[17];
    const float* gbias = (const float*)d_in[18];
    float* out = (float*)d_out;

    cudaFuncSetAttribute(kuv_mma, cudaFuncAttributeMaxDynamicSharedMemorySize, KUV_SMEM);
    cudaFuncSetAttribute(kconv_mma, cudaFuncAttributeMaxDynamicSharedMemorySize, KCV_SMEM);

    kprep<<<7, 128>>>(re, cW, cb, gam, bet, mea, var);
    kprepWc<<<32, 256>>>();
    kprepW<<<128, 256>>>(gW);
    kent<<<(4 * Bsz) / 128, 256>>>(a_ids, e_ids, b_ids, c_ids, nf, ee, nW, nbias);
    kconv_mma<<<(6 * Bsz) / 128, 256, KCV_SMEM>>>(cond, text);
    kuv_mma<<<dim3(4, 2048), 256, KUV_SMEM>>>(gbias, out);
}

// round 17
// speedup vs baseline: 2.3595x; 1.2894x over previous
#include <cuda_runtime.h>
#include <cuda_bf16.h>

#define Bsz   32768
#define Edim  128
#define Fdim  128
#define Gdim  256
#define NFdim 256
#define EPSv  1e-5f

typedef unsigned long long ull;

// ---------------- scratch (device globals: allocation-free; .bss zero-init) ----------
__device__ float g_VALS[(size_t)Bsz * 4 * Edim];     // ent() results, slots 0..3 (64 MB)
// A fragments for stage 3: [split 2][mtB 2048][fb 64][lane 32] uint4  (134 MB)
__device__ uint4 g_XF[(size_t)2 * 2048 * 64 * 32];
// B fragments stage 3: [split 2][ntB 4][fb 128][lane 32] uint2  (256 KB)
__device__ uint2 g_WF[(size_t)2 * 4 * 128 * 32];
// B fragments for kconv_mma (conv weights): [split 2][fb 128][lane 32] uint2 (64 KB)
__device__ uint2 g_WcF[(size_t)2 * 128 * 32];
// B fragments for kent_mma (node_W): [split 2][kc 2][fb 128][lane 32] uint2 (128 KB)
__device__ uint2 g_WnF[(size_t)2 * 2 * 128 * 32];
__device__ float g_C  [6 * Fdim];                    // folded role+bias+BN constant
__device__ float g_WcT[Edim * Fdim];                 // conv_W val-half, transposed, scaled

// ---------------- bf16 split helpers ----------------
__device__ __forceinline__ float bf16f(float a){
    return __bfloat162float(__float2bfloat16_rn(a));
}
__device__ __forceinline__ unsigned pack2(float a, float b){
    unsigned ua = (unsigned)__bfloat16_as_ushort(__float2bfloat16_rn(a));
    unsigned ub = (unsigned)__bfloat16_as_ushort(__float2bfloat16_rn(b));
    return ua | (ub << 16);
}

// bf16 tensor-core MMA: m16n8k16 (sm_80+)
__device__ __forceinline__ void mma_bf16(float* d, const unsigned* a, const unsigned* b){
    asm volatile(
        "mma.sync.aligned.m16n8k16.row.col.f32.bf16.bf16.f32 "
        "{%0,%1,%2,%3}, {%4,%5,%6,%7}, {%8,%9}, {%0,%1,%2,%3};"
        : "+f"(d[0]), "+f"(d[1]), "+f"(d[2]), "+f"(d[3])
        : "r"(a[0]), "r"(a[1]), "r"(a[2]), "r"(a[3]), "r"(b[0]), "r"(b[1]));
}

// ---------------- prep: fold roles + BN into constants ----------------
__global__ void kprep(const float* __restrict__ role_emb, const float* __restrict__ conv_W,
                      const float* __restrict__ conv_b, const float* __restrict__ gam,
                      const float* __restrict__ bet, const float* __restrict__ mea,
                      const float* __restrict__ var)
{
    int f = threadIdx.x;
    float sc = gam[f] * rsqrtf(var[f] + EPSv);
    int blk = blockIdx.x;
    if (blk < 6) {
        const int roles[6] = {0, 1, 2, 3, 4, 6};
        __shared__ float rs[Edim];
        rs[f] = role_emb[roles[blk] * Edim + f];
        __syncthreads();
        float d = 0.f;
        const float* cw = conv_W + f * 2 * Edim;
        #pragma unroll 8
        for (int e = 0; e < Edim; e++) d += rs[e] * cw[e];
        g_C[blk * Fdim + f] = (d + conv_b[f] - mea[f]) * sc + bet[f];
    } else {
        for (int e = 0; e < Edim; e++)
            g_WcT[e * Fdim + f] = conv_W[f * 2 * Edim + Edim + e] * sc;
    }
}

// conv weights -> bf16-split B fragments
__global__ void kprepWc()
{
    int idx = blockIdx.x * 256 + threadIdx.x;   // 0..8191
    int n = idx >> 6, p = idx & 63;
    float v0 = g_WcT[(2 * p) * Fdim + n];
    float v1 = g_WcT[(2 * p + 1) * Fdim + n];
    unsigned hp = pack2(v0, v1);
    unsigned lp = pack2(v0 - bf16f(v0), v1 - bf16f(v1));
    int kst = p >> 3, pi = p & 7, kp = pi & 3, reg = pi >> 2;
    int ntile = n >> 3, lane = (n & 7) * 4 + kp;
    int fb = ntile * 8 + kst;
    unsigned* dst = (unsigned*)g_WcF;
    size_t i0 = ((size_t)fb * 32 + lane) * 2 + reg;
    size_t plane = (size_t)128 * 32 * 2;
    dst[i0] = hp;
    dst[plane + i0] = lp;
}

// node_W -> bf16-split B fragments, 2 K-chunks of 128. B[k][n] = nW[k*Fdim + n].
__global__ void kprepWn(const float* __restrict__ nW)
{
    int idx = blockIdx.x * 256 + threadIdx.x;   // 0..16383
    int n = idx >> 7, p = idx & 127;            // p = k-pair 0..127
    float v0 = nW[(size_t)(2 * p) * Fdim + n];
    float v1 = nW[(size_t)(2 * p + 1) * Fdim + n];
    unsigned hp = pack2(v0, v1);
    unsigned lp = pack2(v0 - bf16f(v0), v1 - bf16f(v1));
    int kc = p >> 6, pl = p & 63;
    int kst = pl >> 3, pi = pl & 7, kp = pi & 3, reg = pi >> 2;
    int ntile = n >> 3, lane = (n & 7) * 4 + kp;
    int fb = ntile * 8 + kst;
    unsigned* dst = (unsigned*)g_WnF;
    size_t i0 = (((size_t)kc * 128 + fb) * 32 + lane) * 2 + reg;
    size_t plane = (size_t)2 * 128 * 32 * 2;
    dst[i0] = hp;
    dst[plane + i0] = lp;
}

// prep gfcn_W into B fragments. n = 2g+h (h=0 -> W1[k][g], h=1 -> W2[k][g]).
__global__ void kprepW(const float* __restrict__ gW)
{
    int idx = blockIdx.x * 256 + threadIdx.x;   // 0..32767
    int n = idx >> 6, p = idx & 63;
    int g = n >> 1, h = n & 1;
    float v0 = gW[(size_t)(h * 128 + 2 * p) * Gdim + g];
    float v1 = gW[(size_t)(h * 128 + 2 * p + 1) * Gdim + g];
    unsigned hp = pack2(v0, v1);
    unsigned lp = pack2(v0 - bf16f(v0), v1 - bf16f(v1));
    int kst = p >> 3, pi = p & 7, kp = pi & 3, reg = pi >> 2;
    int ntB = n >> 7, ntile = (n & 127) >> 3, lane = (n & 7) * 4 + kp;
    int fb = ntile * 8 + kst;
    unsigned* dst = (unsigned*)g_WF;
    size_t i0 = (((size_t)ntB * 128 + fb) * 32 + lane) * 2 + reg;
    size_t plane = (size_t)4 * 128 * 32 * 2;
    dst[i0] = hp;
    dst[plane + i0] = lp;
}

// ---------------- stage 1: gathered ent GEMM as bf16 2-split MMA ----------------
// VALS[R] = relu(nf[sid[R]] @ nW + nbias) + ee[sid[R]],  R = b*4 + slot.
// CTA M128 x N128 x K256 (2 chunks of 128, accumulators persist). grid 1024.
#define KEN_SMEM (131072)
__global__ __launch_bounds__(256, 1) void kent_mma(
    const int* __restrict__ aid, const int* __restrict__ evid,
    const int* __restrict__ bid, const int* __restrict__ cid,
    const float* __restrict__ nf, const float* __restrict__ ee,
    const float* __restrict__ nbias)
{
    extern __shared__ char dsm[];
    uint4* Ah4 = (uint4*)dsm;                     // 64 fb * 32 * 16B = 32KB
    uint4* Al4 = (uint4*)(dsm + 32768);
    uint2* Bh2 = (uint2*)(dsm + 65536);           // 128 fb * 32 * 8B = 32KB
    uint2* Bl2 = (uint2*)(dsm + 98304);
    __shared__ int sid[128];
    int t = threadIdx.x, w = t >> 5, l = t & 31;
    int mtB = blockIdx.x;
    int r0 = mtB * 128;

    if (t < 128) {
        int R = r0 + t;
        int b = R >> 2, j = R & 3;
        const int* p = (j == 0) ? aid : (j == 1) ? evid : (j == 2) ? bid : cid;
        sid[t] = p[b];
    }
    __syncthreads();

    int wmFb = (w >> 2) * 32;
    int wnFb = (w & 3) * 32;
    float d[4][4][4];
    #pragma unroll
    for (int mi = 0; mi < 4; mi++)
        #pragma unroll
        for (int ni = 0; ni < 4; ni++)
            #pragma unroll
            for (int r = 0; r < 4; r++) d[mi][ni][r] = 0.f;

    for (int kc = 0; kc < 2; kc++) {
        if (kc) __syncthreads();   // protect previous chunk's fragments until consumed
        // A fill: gather nf rows, convert fp32 -> bf16 hi/lo fragment pairs
        {
            unsigned* AhU = (unsigned*)Ah4;
            unsigned* AlU = (unsigned*)Al4;
            #pragma unroll
            for (int it = 0; it < 16; it++) {
                int u = t + it * 256;             // (row, k-quad)
                int row = u >> 5, kq = (u & 31) << 2;
                float4 v = *(const float4*)(nf + (size_t)sid[row] * NFdim + kc * 128 + kq);
                int mtile = row >> 4, rin = row & 15;
                int kst = kq >> 4, klocal = kq & 15;
                int reg = (rin >> 3) + ((klocal >> 3) << 1);
                int lane = (rin & 7) * 4 + ((klocal & 7) >> 1);
                int base = ((mtile * 8 + kst) * 32 + lane) * 4 + reg;
                AhU[base]     = pack2(v.x, v.y);
                AhU[base + 4] = pack2(v.z, v.w);
                AlU[base]     = pack2(v.x - bf16f(v.x), v.y - bf16f(v.y));
                AlU[base + 4] = pack2(v.z - bf16f(v.z), v.w - bf16f(v.w));
            }
        }
        // B fill: plain copies of precomputed fragments (32KB per split per chunk)
        {
            const uint4* sBh = ((const uint4*)g_WnF) + (size_t)kc * 2048;
            const uint4* sBl = ((const uint4*)g_WnF) + (size_t)(4096 + kc * 2048);
            uint4* dBh = (uint4*)Bh2;
            uint4* dBl = (uint4*)Bl2;
            #pragma unroll
            for (int it = 0; it < 8; it++) {
                int u = t + it * 256;
                dBh[u] = sBh[u];
                dBl[u] = sBl[u];
            }
        }
        __syncthreads();

        #pragma unroll
        for (int ks = 0; ks < 8; ks++) {
            uint4 ah[4], al[4]; uint2 bh[4], bl[4];
            #pragma unroll
            for (int mi = 0; mi < 4; mi++) {
                ah[mi] = Ah4[(wmFb + mi * 8 + ks) * 32 + l];
                al[mi] = Al4[(wmFb + mi * 8 + ks) * 32 + l];
            }
            #pragma unroll
            for (int ni = 0; ni < 4; ni++) {
                bh[ni] = Bh2[(wnFb + ni * 8 + ks) * 32 + l];
                bl[ni] = Bl2[(wnFb + ni * 8 + ks) * 32 + l];
            }
            #pragma unroll
            for (int mi = 0; mi < 4; mi++)
                #pragma unroll
                for (int ni = 0; ni < 4; ni++) {
                    mma_bf16(d[mi][ni], (const unsigned*)&al[mi], (const unsigned*)&bh[ni]);
                    mma_bf16(d[mi][ni], (const unsigned*)&ah[mi], (const unsigned*)&bl[ni]);
                    mma_bf16(d[mi][ni], (const unsigned*)&ah[mi], (const unsigned*)&bh[ni]);
                }
        }
    }

    // ---- epilogue: relu(+nbias) + ee gather, fp32 writes to g_VALS ----
    int mrowBase = (w >> 2) * 64 + (l >> 2);
    int fBase = (w & 3) * 32 + (l & 3) * 2;
    #pragma unroll
    for (int mi = 0; mi < 4; mi++) {
        #pragma unroll
        for (int rh = 0; rh < 2; rh++) {
            int row = mrowBase + mi * 16 + rh * 8;
            int R = r0 + row;
            const float* eer = ee + (size_t)sid[row] * Edim;
            #pragma unroll
            for (int ni = 0; ni < 4; ni++) {
                int f0 = fBase + ni * 8;
                float2 nb2 = *(const float2*)(nbias + f0);
                float2 e2 = *(const float2*)(eer + f0);
                float2 o;
                o.x = fmaxf(d[mi][ni][rh * 2 + 0] + nb2.x, 0.f) + e2.x;
                o.y = fmaxf(d[mi][ni][rh * 2 + 1] + nb2.y, 0.f) + e2.y;
                *(float2*)(g_VALS + (size_t)R * Edim + f0) = o;
            }
        }
    }
}

// ---------------- stage 2: conv+BN+relu as bf16 2-split MMA, frag-in / frag-out ------
#define KCV_SMEM (131072)
__global__ __launch_bounds__(256, 1) void kconv_mma(const float* __restrict__ cond,
                                                    const float* __restrict__ text)
{
    extern __shared__ char dsm[];
    uint4* Ah4 = (uint4*)dsm;
    uint4* Al4 = (uint4*)(dsm + 32768);
    uint2* Bh2 = (uint2*)(dsm + 65536);
    uint2* Bl2 = (uint2*)(dsm + 98304);
    __shared__ const float* srcp[128];
    int t = threadIdx.x, w = t >> 5, l = t & 31;
    int mtB = blockIdx.x;
    int r0 = mtB * 128;

    if (t < 128) {
        int r = r0 + t;
        int b = r / 6, s = r - b * 6;
        const float* p;
        if (s < 4)       p = g_VALS + ((size_t)b * 4 + s) * Edim;
        else if (s == 4) p = cond + (size_t)b * Edim;
        else             p = text + (size_t)b * Edim;
        srcp[t] = p;
    }
    {
        const uint4* sBh = (const uint4*)g_WcF;
        const uint4* sBl = ((const uint4*)g_WcF) + 2048;
        uint4* dBh = (uint4*)Bh2;
        uint4* dBl = (uint4*)Bl2;
        #pragma unroll
        for (int it = 0; it < 8; it++) {
            int u = t + it * 256;
            dBh[u] = sBh[u];
            dBl[u] = sBl[u];
        }
    }
    __syncthreads();
    {
        unsigned* AhU = (unsigned*)Ah4;
        unsigned* AlU = (unsigned*)Al4;
        #pragma unroll
        for (int it = 0; it < 16; it++) {
            int u = t + it * 256;
            int row = u >> 5, kq = (u & 31) << 2;
            float4 v = *(const float4*)(srcp[row] + kq);
            int mtile = row >> 4, rin = row & 15;
            int kst = kq >> 4, klocal = kq & 15;
            int reg = (rin >> 3) + ((klocal >> 3) << 1);
            int lane = (rin & 7) * 4 + ((klocal & 7) >> 1);
            int base = ((mtile * 8 + kst) * 32 + lane) * 4 + reg;
            AhU[base]     = pack2(v.x, v.y);
            AhU[base + 4] = pack2(v.z, v.w);
            AlU[base]     = pack2(v.x - bf16f(v.x), v.y - bf16f(v.y));
            AlU[base + 4] = pack2(v.z - bf16f(v.z), v.w - bf16f(v.w));
        }
    }
    __syncthreads();

    int wmFb = (w >> 2) * 32;
    int wnFb = (w & 3) * 32;
    float d[4][4][4];
    #pragma unroll
    for (int mi = 0; mi < 4; mi++)
        #pragma unroll
        for (int ni = 0; ni < 4; ni++)
            #pragma unroll
            for (int r = 0; r < 4; r++) d[mi][ni][r] = 0.f;

    #pragma unroll
    for (int ks = 0; ks < 8; ks++) {
        uint4 ah[4], al[4]; uint2 bh[4], bl[4];
        #pragma unroll
        for (int mi = 0; mi < 4; mi++) {
            ah[mi] = Ah4[(wmFb + mi * 8 + ks) * 32 + l];
            al[mi] = Al4[(wmFb + mi * 8 + ks) * 32 + l];
        }
        #pragma unroll
        for (int ni = 0; ni < 4; ni++) {
            bh[ni] = Bh2[(wnFb + ni * 8 + ks) * 32 + l];
            bl[ni] = Bl2[(wnFb + ni * 8 + ks) * 32 + l];
        }
        #pragma unroll
        for (int mi = 0; mi < 4; mi++)
            #pragma unroll
            for (int ni = 0; ni < 4; ni++) {
                mma_bf16(d[mi][ni], (const unsigned*)&al[mi], (const unsigned*)&bh[ni]);
                mma_bf16(d[mi][ni], (const unsigned*)&ah[mi], (const unsigned*)&bl[ni]);
                mma_bf16(d[mi][ni], (const unsigned*)&ah[mi], (const unsigned*)&bh[ni]);
            }
    }

    int mrowBase = (w >> 2) * 64 + (l >> 2);
    int fBase = (w & 3) * 32 + (l & 3) * 2;
    unsigned* dstg = (unsigned*)g_XF;
    const size_t plane = (size_t)2048 * 64 * 32 * 4;
    #pragma unroll
    for (int mi = 0; mi < 4; mi++) {
        #pragma unroll
        for (int rh = 0; rh < 2; rh++) {
            int R6 = r0 + mrowBase + mi * 16 + rh * 8;
            int b6 = R6 / 6, s6 = R6 - b6 * 6;
            int R8 = b6 * 8 + s6;
            int omtB = R8 >> 7, orloc = R8 & 127;
            int omtile = orloc >> 4, orin = orloc & 15;
            int ocreg0 = orin >> 3;
            int olanebase = (orin & 7) * 4;
            #pragma unroll
            for (int ni = 0; ni < 4; ni++) {
                int f0 = fBase + ni * 8;
                float2 cc = *(const float2*)(g_C + s6 * Fdim + f0);
                float v0 = fmaxf(d[mi][ni][rh * 2 + 0] + cc.x, 0.f);
                float v1 = fmaxf(d[mi][ni][rh * 2 + 1] + cc.y, 0.f);
                int okst = f0 >> 4, okl = f0 & 15;
                int ocreg = ocreg0 + ((okl >> 3) << 1);
                int olane = olanebase + ((okl & 7) >> 1);
                size_t idx = (((size_t)omtB * 64 + omtile * 8 + okst) * 32 + olane) * 4
                           + ocreg;
                dstg[idx] = pack2(v0, v1);
                dstg[plane + idx] = pack2(v0 - bf16f(v0), v1 - bf16f(v1));
            }
        }
    }
}

// ---------------- stage 3: bf16 2-split m16n8k16 MMA + min-over-6 + relu out ---------
#define KUV_SMEM (131072)
__global__ __launch_bounds__(256, 1) void kuv_mma(const float* __restrict__ gb,
                                                  float* __restrict__ out)
{
    extern __shared__ char dsm[];
    uint4* Ah4 = (uint4*)dsm;
    uint4* Al4 = (uint4*)(dsm + 32768);
    uint2* Bh2 = (uint2*)(dsm + 65536);
    uint2* Bl2 = (uint2*)(dsm + 98304);
    int t = threadIdx.x, w = t >> 5, l = t & 31;
    int ntB = blockIdx.x, mtB = blockIdx.y;

    {
        const uint4* sAh = g_XF + (size_t)mtB * 2048;
        const uint4* sAl = g_XF + (size_t)(2048 + mtB) * 2048;
        #pragma unroll
        for (int it = 0; it < 8; it++) {
            int u = t + it * 256;
            Ah4[u] = sAh[u];
            Al4[u] = sAl[u];
        }
        const uint4* sBh = (const uint4*)(g_WF + (size_t)ntB * 4096);
        const uint4* sBl = (const uint4*)(g_WF + (size_t)(16384 + ntB * 4096));
        uint4* dBh = (uint4*)Bh2;
        uint4* dBl = (uint4*)Bl2;
        #pragma unroll
        for (int it = 0; it < 8; it++) {
            int u = t + it * 256;
            dBh[u] = sBh[u];
            dBl[u] = sBl[u];
        }
    }
    __syncthreads();

    int wmFb = (w >> 2) * 32;
    int wnFb = (w & 3) * 32;
    float d[4][4][4];
    #pragma unroll
    for (int mi = 0; mi < 4; mi++)
        #pragma unroll
        for (int ni = 0; ni < 4; ni++)
            #pragma unroll
            for (int r = 0; r < 4; r++) d[mi][ni][r] = 0.f;

    #pragma unroll
    for (int ks = 0; ks < 8; ks++) {
        uint4 ah[4], al[4]; uint2 bh[4], bl[4];
        #pragma unroll
        for (int mi = 0; mi < 4; mi++) {
            ah[mi] = Ah4[(wmFb + mi * 8 + ks) * 32 + l];
            al[mi] = Al4[(wmFb + mi * 8 + ks) * 32 + l];
        }
        #pragma unroll
        for (int ni = 0; ni < 4; ni++) {
            bh[ni] = Bh2[(wnFb + ni * 8 + ks) * 32 + l];
            bl[ni] = Bl2[(wnFb + ni * 8 + ks) * 32 + l];
        }
        #pragma unroll
        for (int mi = 0; mi < 4; mi++)
            #pragma unroll
            for (int ni = 0; ni < 4; ni++) {
                mma_bf16(d[mi][ni], (const unsigned*)&al[mi], (const unsigned*)&bh[ni]);
                mma_bf16(d[mi][ni], (const unsigned*)&ah[mi], (const unsigned*)&bl[ni]);
                mma_bf16(d[mi][ni], (const unsigned*)&ah[mi], (const unsigned*)&bh[ni]);
            }
    }

    int slot = l >> 2, c = l & 3;
    if (slot >= 6) {
        #pragma unroll
        for (int mi = 0; mi < 4; mi++)
            #pragma unroll
            for (int ni = 0; ni < 4; ni++)
                #pragma unroll
                for (int r = 0; r < 4; r++) d[mi][ni][r] = 1e30f;
    }
    #pragma unroll
    for (int mi = 0; mi < 4; mi++)
        #pragma unroll
        for (int ni = 0; ni < 4; ni++)
            #pragma unroll
            for (int r = 0; r < 4; r++) {
                float v = d[mi][ni][r];
                v = fminf(v, __shfl_xor_sync(0xFFFFFFFFu, v, 4));
                v = fminf(v, __shfl_xor_sync(0xFFFFFFFFu, v, 8));
                v = fminf(v, __shfl_xor_sync(0xFFFFFFFFu, v, 16));
                d[mi][ni][r] = v;
            }

    int gBase = ntB * 64 + (w & 3) * 16;
    float gbv[4];
    #pragma unroll
    for (int ni = 0; ni < 4; ni++) gbv[ni] = gb[gBase + ni * 4 + c];

    int bbBase = mtB * 16 + (w >> 2) * 8;
    #pragma unroll
    for (int mi = 0; mi < 4; mi++) {
        #pragma unroll
        for (int half = 0; half < 2; half++) {
            int bb = bbBase + mi * 2 + half;
            bool mine = (slot == half * 4 + mi);
            #pragma unroll
            for (int ni = 0; ni < 4; ni++) {
                float uu = d[mi][ni][half * 2 + 0];
                float vv = d[mi][ni][half * 2 + 1];
                float o = fmaxf(uu + vv + gbv[ni], 0.f);
                if (mine) out[(size_t)bb * Gdim + gBase + ni * 4 + c] = o;
            }
        }
    }
}

// ---------------- launcher ----------------
extern "C" void kernel_launch(void* const* d_in, const int* in_sizes, int n_in,
                              void* d_out, int out_size)
{
    const int*   a_ids = (const int*)d_in[0];
    const int*   b_ids = (const int*)d_in[1];
    const int*   c_ids = (const int*)d_in[2];
    const int*   e_ids = (const int*)d_in[3];
    const float* nf    = (const float*)d_in[4];
    const float* cond  = (const float*)d_in[5];
    const float* text  = (const float*)d_in[6];
    const float* ee    = (const float*)d_in[7];
    const float* re    = (const float*)d_in[8];
    const float* nW    = (const float*)d_in[9];
    const float* nbias = (const float*)d_in[10];
    const float* cW    = (const float*)d_in[11];
    const float* cb    = (const float*)d_in[12];
    const float* gam   = (const float*)d_in[13];
    const float* bet   = (const float*)d_in[14];
    const float* mea   = (const float*)d_in[15];
    const float* var   = (const float*)d_in[16];
    const float* gW    = (const float*)d_in[17];
    const float* gbias = (const float*)d_in[18];
    float* out = (float*)d_out;

    cudaFuncSetAttribute(kuv_mma, cudaFuncAttributeMaxDynamicSharedMemorySize, KUV_SMEM);
    cudaFuncSetAttribute(kconv_mma, cudaFuncAttributeMaxDynamicSharedMemorySize, KCV_SMEM);
    cudaFuncSetAttribute(kent_mma, cudaFuncAttributeMaxDynamicSharedMemorySize, KEN_SMEM);

    kprep<<<7, 128>>>(re, cW, cb, gam, bet, mea, var);
    kprepWc<<<32, 256>>>();
    kprepWn<<<64, 256>>>(nW);
    kprepW<<<128, 256>>>(gW);
    kent_mma<<<(4 * Bsz) / 128, 256, KEN_SMEM>>>(a_ids, e_ids, b_ids, c_ids, nf, ee, nbias);
    kconv_mma<<<(6 * Bsz) / 128, 256, KCV_SMEM>>>(cond, text);
    kuv_mma<<<dim3(4, 2048), 256, KUV_SMEM>>>(gbias, out);
}